// round 1
// baseline (speedup 1.0000x reference)
#include <cuda_runtime.h>

#define NB    4
#define TSEQ  2048
#define CDIM  1024
#define HEADS 16
#define HD    64
#define BT    (NB*TSEQ)          // 8192 rows
#define NQKV  3072               // only first 3C rows of w_attn used

// Scratch (96 MB total) — __device__ globals, no runtime allocation.
__device__ float g_q[(size_t)NB*HEADS*TSEQ*HD];
__device__ float g_k[(size_t)NB*HEADS*TSEQ*HD];
__device__ float g_v[(size_t)NB*HEADS*TSEQ*HD];

// ---------------------------------------------------------------------------
// Kernel 1: qkv = x @ w[0:3072].T + b, scattered into [B,H,T,D] Q/K/V layout.
// 128x128x16 tile, 256 threads, 8x8 microtile per thread.
// ---------------------------------------------------------------------------
__global__ __launch_bounds__(256) void qkv_gemm(const float* __restrict__ x,
                                                const float* __restrict__ w,
                                                const float* __restrict__ bias)
{
    __shared__ float As[16][128];
    __shared__ float Bs[16][128];

    const int tid = threadIdx.x;
    const int m0  = blockIdx.y * 128;
    const int n0  = blockIdx.x * 128;
    const int tr  = tid >> 4;          // 0..15
    const int tc  = tid & 15;          // 0..15
    const int lr  = tid >> 2;          // 0..63
    const int lk  = (tid & 3) << 2;    // 0,4,8,12

    float acc[8][8];
#pragma unroll
    for (int i = 0; i < 8; i++)
#pragma unroll
        for (int j = 0; j < 8; j++) acc[i][j] = 0.f;

    for (int k0 = 0; k0 < CDIM; k0 += 16) {
#pragma unroll
        for (int p = 0; p < 2; p++) {
            const int row = lr + p * 64;
            float4 va = *(const float4*)(&x[(size_t)(m0 + row) * CDIM + k0 + lk]);
            As[lk + 0][row] = va.x;
            As[lk + 1][row] = va.y;
            As[lk + 2][row] = va.z;
            As[lk + 3][row] = va.w;
            float4 vb = *(const float4*)(&w[(size_t)(n0 + row) * CDIM + k0 + lk]);
            Bs[lk + 0][row] = vb.x;
            Bs[lk + 1][row] = vb.y;
            Bs[lk + 2][row] = vb.z;
            Bs[lk + 3][row] = vb.w;
        }
        __syncthreads();

#pragma unroll
        for (int k = 0; k < 16; k++) {
            float a[8], b[8];
            *(float4*)&a[0] = *(const float4*)&As[k][tr * 8];
            *(float4*)&a[4] = *(const float4*)&As[k][tr * 8 + 4];
            *(float4*)&b[0] = *(const float4*)&Bs[k][tc * 8];
            *(float4*)&b[4] = *(const float4*)&Bs[k][tc * 8 + 4];
#pragma unroll
            for (int i = 0; i < 8; i++)
#pragma unroll
                for (int j = 0; j < 8; j++)
                    acc[i][j] = fmaf(a[i], b[j], acc[i][j]);
        }
        __syncthreads();
    }

    // Epilogue: +bias, scatter to q/k/v in [B,H,T,D]
#pragma unroll
    for (int j = 0; j < 8; j++) {
        const int n   = n0 + tc * 8 + j;
        const float bn = bias[n];
        const int region = n >> 10;        // 0:q 1:k 2:v
        const int nn = n & 1023;
        const int h  = nn >> 6;
        const int d  = nn & 63;
        float* dst = (region == 0) ? g_q : (region == 1) ? g_k : g_v;
#pragma unroll
        for (int i = 0; i < 8; i++) {
            const int m = m0 + tr * 8 + i;
            const int b = m >> 11;         // /2048
            const int t = m & 2047;
            dst[(((size_t)b * HEADS + h) * TSEQ + t) * HD + d] = acc[i][j] + bn;
        }
    }
}

// ---------------------------------------------------------------------------
// Kernel 2: flash-attention forward, fp32.
// Grid: (T/64, B*H). 256 threads as 16x16; each thread owns a 4x4 tile of
// the 64x64 S block and a 4(rows)x4(D-cols) slice of the O block.
// smem: Qs/Ks/Vs [64][65] (pad 65 => conflict-free). P aliases Ks.
// ---------------------------------------------------------------------------
#define SPAD 65

__global__ __launch_bounds__(256) void attn_fwd(float* __restrict__ out)
{
    extern __shared__ float sm[];
    float* Qs = sm;                 // [64][65]
    float* Ks = sm + 64 * SPAD;     // [64][65], reused as P after S compute
    float* Vs = sm + 2 * 64 * SPAD; // [64][65]

    const int tid = threadIdx.x;
    const int ty  = tid >> 4;       // 0..15 (row group)
    const int tx  = tid & 15;       // 0..15 (col group)
    const int qb  = blockIdx.x;
    const int bh  = blockIdx.y;

    const float* qg = g_q + ((size_t)bh * TSEQ + qb * 64) * HD;
    const float* kg = g_k + (size_t)bh * TSEQ * HD;
    const float* vg = g_v + (size_t)bh * TSEQ * HD;

    // Load Q tile, pre-scaled by 1/sqrt(D)
    for (int idx = tid; idx < 1024; idx += 256) {
        const int row = idx >> 4;
        const int cg  = (idx & 15) << 2;
        float4 v = *(const float4*)(qg + row * HD + cg);
        float* q = &Qs[row * SPAD + cg];
        q[0] = v.x * 0.125f; q[1] = v.y * 0.125f;
        q[2] = v.z * 0.125f; q[3] = v.w * 0.125f;
    }

    float o[4][4];
    float mrow[4], lrow[4];
#pragma unroll
    for (int r = 0; r < 4; r++) {
        mrow[r] = -1e30f; lrow[r] = 0.f;
#pragma unroll
        for (int c = 0; c < 4; c++) o[r][c] = 0.f;
    }

    for (int kb = 0; kb <= qb; kb++) {
        __syncthreads();   // previous iter done with Ks(P)/Vs; also fences Q load on iter 0 via next sync
        for (int idx = tid; idx < 1024; idx += 256) {
            const int row = idx >> 4;
            const int cg  = (idx & 15) << 2;
            float4 kv = *(const float4*)(kg + (size_t)(kb * 64 + row) * HD + cg);
            float* kd = &Ks[row * SPAD + cg];
            kd[0] = kv.x; kd[1] = kv.y; kd[2] = kv.z; kd[3] = kv.w;
            float4 vv = *(const float4*)(vg + (size_t)(kb * 64 + row) * HD + cg);
            float* vd = &Vs[row * SPAD + cg];
            vd[0] = vv.x; vd[1] = vv.y; vd[2] = vv.z; vd[3] = vv.w;
        }
        __syncthreads();

        // S = (Q * scale) @ K^T, 4x4 per thread
        float s[4][4];
#pragma unroll
        for (int r = 0; r < 4; r++)
#pragma unroll
            for (int c = 0; c < 4; c++) s[r][c] = 0.f;

#pragma unroll 8
        for (int d = 0; d < HD; d++) {
            float a[4], b[4];
#pragma unroll
            for (int r = 0; r < 4; r++) a[r] = Qs[(ty * 4 + r) * SPAD + d];
#pragma unroll
            for (int c = 0; c < 4; c++) b[c] = Ks[(tx * 4 + c) * SPAD + d];
#pragma unroll
            for (int r = 0; r < 4; r++)
#pragma unroll
                for (int c = 0; c < 4; c++)
                    s[r][c] = fmaf(a[r], b[c], s[r][c]);
        }

        // causal mask on diagonal block
        if (kb == qb) {
#pragma unroll
            for (int r = 0; r < 4; r++)
#pragma unroll
                for (int c = 0; c < 4; c++)
                    if (tx * 4 + c > ty * 4 + r) s[r][c] = -1e30f;
        }

        // online softmax (row reductions across the 16 threads sharing a row)
#pragma unroll
        for (int r = 0; r < 4; r++) {
            float mx = fmaxf(fmaxf(s[r][0], s[r][1]), fmaxf(s[r][2], s[r][3]));
#pragma unroll
            for (int off = 1; off < 16; off <<= 1)
                mx = fmaxf(mx, __shfl_xor_sync(0xffffffffu, mx, off));
            const float mnew  = fmaxf(mrow[r], mx);
            const float alpha = __expf(mrow[r] - mnew);
            float rs = 0.f;
#pragma unroll
            for (int c = 0; c < 4; c++) {
                s[r][c] = __expf(s[r][c] - mnew);
                rs += s[r][c];
            }
#pragma unroll
            for (int off = 1; off < 16; off <<= 1)
                rs += __shfl_xor_sync(0xffffffffu, rs, off);
            lrow[r] = lrow[r] * alpha + rs;
            mrow[r] = mnew;
#pragma unroll
            for (int c = 0; c < 4; c++) o[r][c] *= alpha;
        }

        __syncthreads();   // everyone done reading Ks; safe to overwrite with P
#pragma unroll
        for (int r = 0; r < 4; r++)
#pragma unroll
            for (int c = 0; c < 4; c++)
                Ks[(ty * 4 + r) * SPAD + tx * 4 + c] = s[r][c];
        __syncthreads();

        // O += P @ V   (P in Ks buffer)
#pragma unroll 8
        for (int c = 0; c < 64; c++) {
            float p[4], vv[4];
#pragma unroll
            for (int r = 0; r < 4; r++) p[r] = Ks[(ty * 4 + r) * SPAD + c];
#pragma unroll
            for (int j = 0; j < 4; j++) vv[j] = Vs[c * SPAD + tx * 4 + j];
#pragma unroll
            for (int r = 0; r < 4; r++)
#pragma unroll
                for (int j = 0; j < 4; j++)
                    o[r][j] = fmaf(p[r], vv[j], o[r][j]);
        }
    }

    // write out[b][t][h*64+d]
    const int b = bh >> 4;
    const int h = bh & 15;
#pragma unroll
    for (int r = 0; r < 4; r++) {
        const int t = qb * 64 + ty * 4 + r;
        const float inv = 1.0f / lrow[r];
        float4 vo;
        vo.x = o[r][0] * inv; vo.y = o[r][1] * inv;
        vo.z = o[r][2] * inv; vo.w = o[r][3] * inv;
        *(float4*)(&out[(size_t)(b * TSEQ + t) * CDIM + h * HD + tx * 4]) = vo;
    }
}

// ---------------------------------------------------------------------------
extern "C" void kernel_launch(void* const* d_in, const int* in_sizes, int n_in,
                              void* d_out, int out_size)
{
    (void)in_sizes; (void)n_in; (void)out_size;
    const float* x  = (const float*)d_in[0];
    const float* w  = (const float*)d_in[1];
    const float* bb = (const float*)d_in[2];
    float* out = (float*)d_out;

    dim3 gg(NQKV / 128, BT / 128);            // (24, 64)
    qkv_gemm<<<gg, 256>>>(x, w, bb);

    const int smem = 3 * 64 * SPAD * (int)sizeof(float);   // 49920 B
    cudaFuncSetAttribute((const void*)attn_fwd,
                         cudaFuncAttributeMaxDynamicSharedMemorySize, smem);
    dim3 ga(TSEQ / 64, NB * HEADS);           // (32, 64)
    attn_fwd<<<ga, 256, smem>>>(out);
}

// round 3
// speedup vs baseline: 3.0670x; 3.0670x over previous
#include <cuda_runtime.h>
#include <cuda_bf16.h>
#include <cstdint>

#define NB    4
#define TSEQ  2048
#define CDIM  1024
#define HEADS 16
#define HD    64
#define BT    (NB*TSEQ)          // 8192
#define NQKV  3072

// ---------------------------------------------------------------------------
// __device__ global scratch (no runtime allocation)
// ---------------------------------------------------------------------------
__device__ __nv_bfloat16 g_xh[(size_t)BT*CDIM];
__device__ __nv_bfloat16 g_xl[(size_t)BT*CDIM];
__device__ __nv_bfloat16 g_wh[(size_t)NQKV*CDIM];
__device__ __nv_bfloat16 g_wl[(size_t)NQKV*CDIM];
// Q/K/V in [B,H,T,D], bf16 hi/lo pairs (Q pre-scaled by 1/8)
__device__ __nv_bfloat16 g_qh[(size_t)NB*HEADS*TSEQ*HD];
__device__ __nv_bfloat16 g_ql[(size_t)NB*HEADS*TSEQ*HD];
__device__ __nv_bfloat16 g_kh[(size_t)NB*HEADS*TSEQ*HD];
__device__ __nv_bfloat16 g_kl[(size_t)NB*HEADS*TSEQ*HD];
__device__ __nv_bfloat16 g_vh[(size_t)NB*HEADS*TSEQ*HD];
__device__ __nv_bfloat16 g_vl[(size_t)NB*HEADS*TSEQ*HD];

// ---------------------------------------------------------------------------
// Helpers (sm_80-class ISA only: mma.sync / ldmatrix / cp.async)
// ---------------------------------------------------------------------------
__device__ __forceinline__ uint32_t smem_to_u32(const void* p) {
    uint32_t a;
    asm("{ .reg .u64 t; cvta.to.shared.u64 t, %1; cvt.u32.u64 %0, t; }" : "=r"(a) : "l"(p));
    return a;
}
#define CP_ASYNC(dst, src) \
    asm volatile("cp.async.cg.shared.global [%0], [%1], 16;\n" :: "r"(dst), "l"(src))
#define CP_COMMIT() asm volatile("cp.async.commit_group;\n" ::: "memory")
#define CP_WAIT1()  asm volatile("cp.async.wait_group 1;\n" ::: "memory")
#define CP_WAIT0()  asm volatile("cp.async.wait_group 0;\n" ::: "memory")

__device__ __forceinline__ void ldsm4(uint32_t r[4], uint32_t a) {
    asm volatile("ldmatrix.sync.aligned.m8n8.x4.shared.b16 {%0,%1,%2,%3}, [%4];"
                 : "=r"(r[0]), "=r"(r[1]), "=r"(r[2]), "=r"(r[3]) : "r"(a));
}
__device__ __forceinline__ void ldsm4t(uint32_t r[4], uint32_t a) {
    asm volatile("ldmatrix.sync.aligned.m8n8.x4.trans.shared.b16 {%0,%1,%2,%3}, [%4];"
                 : "=r"(r[0]), "=r"(r[1]), "=r"(r[2]), "=r"(r[3]) : "r"(a));
}
__device__ __forceinline__ void mma_bf16(float c[4], const uint32_t a[4],
                                         uint32_t b0, uint32_t b1) {
    asm volatile("mma.sync.aligned.m16n8k16.row.col.f32.bf16.bf16.f32 "
                 "{%0,%1,%2,%3}, {%4,%5,%6,%7}, {%8,%9}, {%0,%1,%2,%3};"
                 : "+f"(c[0]), "+f"(c[1]), "+f"(c[2]), "+f"(c[3])
                 : "r"(a[0]), "r"(a[1]), "r"(a[2]), "r"(a[3]), "r"(b0), "r"(b1));
}
__device__ __forceinline__ uint32_t pack2(__nv_bfloat16 lo, __nv_bfloat16 hi) {
    __nv_bfloat162 t(lo, hi);
    return *reinterpret_cast<uint32_t*>(&t);
}

// ---------------------------------------------------------------------------
// Kernel 0: split fp32 -> bf16 hi/lo
// ---------------------------------------------------------------------------
__global__ __launch_bounds__(256) void split_bf16(const float* __restrict__ src,
                                                  __nv_bfloat16* __restrict__ hi,
                                                  __nv_bfloat16* __restrict__ lo,
                                                  int n4)
{
    int i = blockIdx.x * 256 + threadIdx.x;
    if (i >= n4) return;
    float4 v = ((const float4*)src)[i];
    __nv_bfloat16 h0 = __float2bfloat16(v.x), h1 = __float2bfloat16(v.y);
    __nv_bfloat16 h2 = __float2bfloat16(v.z), h3 = __float2bfloat16(v.w);
    __nv_bfloat16 l0 = __float2bfloat16(v.x - __bfloat162float(h0));
    __nv_bfloat16 l1 = __float2bfloat16(v.y - __bfloat162float(h1));
    __nv_bfloat16 l2 = __float2bfloat16(v.z - __bfloat162float(h2));
    __nv_bfloat16 l3 = __float2bfloat16(v.w - __bfloat162float(h3));
    __nv_bfloat162* hp = (__nv_bfloat162*)hi;
    __nv_bfloat162* lp = (__nv_bfloat162*)lo;
    hp[2*i]   = __nv_bfloat162(h0, h1);
    hp[2*i+1] = __nv_bfloat162(h2, h3);
    lp[2*i]   = __nv_bfloat162(l0, l1);
    lp[2*i+1] = __nv_bfloat162(l2, l3);
}

// ---------------------------------------------------------------------------
// Kernel 1: QKV GEMM via mma.sync bf16x3. CTA 128x128, KC=32, double buffer.
// smem tiles row-padded to 80B (conflict-free ldmatrix). Epilogue: +bias,
// Q-scale, bf16 hi/lo split, scatter to [B,H,T,D].
// ---------------------------------------------------------------------------
#define KCG      32
#define GSTR_B   80                 // bytes per smem row (32 bf16 + pad)
#define GTILE_B  (128*GSTR_B)       // 10240
#define GBUF_B   (4*GTILE_B)        // 40960

__device__ __forceinline__ void gemm_load(uint32_t sdst, int tid, int k0, int m0, int n0)
{
#pragma unroll
    for (int i = 0; i < 8; i++) {
        const int tile = i >> 1;                   // 0 xh, 1 xl, 2 wh, 3 wl
        int rem = ((i & 1) << 8) + tid;            // 0..511
        int row = rem >> 2, q = tid & 3;
        const __nv_bfloat16* g =
            (tile == 0) ? g_xh + (size_t)(m0 + row) * CDIM :
            (tile == 1) ? g_xl + (size_t)(m0 + row) * CDIM :
            (tile == 2) ? g_wh + (size_t)(n0 + row) * CDIM :
                          g_wl + (size_t)(n0 + row) * CDIM;
        CP_ASYNC(sdst + tile * GTILE_B + row * GSTR_B + q * 16, g + k0 + q * 8);
    }
}

__global__ __launch_bounds__(256, 2) void qkv_gemm_mma(const float* __restrict__ bias)
{
    extern __shared__ char smg[];
    const uint32_t sbase = smem_to_u32(smg);
    const int tid = threadIdx.x, lane = tid & 31, wid = tid >> 5;
    const int m0 = blockIdx.y * 128, n0 = blockIdx.x * 128;
    const int wm = wid & 3, wn = wid >> 2;

    float acc[2][8][4];
#pragma unroll
    for (int mi = 0; mi < 2; mi++)
#pragma unroll
        for (int nj = 0; nj < 8; nj++)
#pragma unroll
            for (int c = 0; c < 4; c++) acc[mi][nj][c] = 0.f;

    gemm_load(sbase, tid, 0, m0, n0);
    CP_COMMIT();

    const int NCH = CDIM / KCG;     // 32
    for (int c = 0; c < NCH; c++) {
        const int buf = c & 1;
        if (c + 1 < NCH) {
            gemm_load(sbase + (buf ^ 1) * GBUF_B, tid, (c + 1) * KCG, m0, n0);
            CP_COMMIT();
            CP_WAIT1();
        } else {
            CP_WAIT0();
        }
        __syncthreads();

        const uint32_t bb = sbase + buf * GBUF_B;
#pragma unroll
        for (int ks = 0; ks < 2; ks++) {
            const uint32_t coff = (ks * 16 + ((lane >> 4) << 3)) * 2;
            uint32_t ah[2][4], al[2][4];
#pragma unroll
            for (int mi = 0; mi < 2; mi++) {
                uint32_t ra = bb + (wm * 32 + mi * 16 + (lane & 15)) * GSTR_B + coff;
                ldsm4(ah[mi], ra);
                ldsm4(al[mi], ra + GTILE_B);
            }
#pragma unroll
            for (int g2 = 0; g2 < 4; g2++) {
                uint32_t bh4[4], bl4[4];
                uint32_t rb = bb + 2 * GTILE_B +
                              (wn * 64 + g2 * 16 + (lane & 15)) * GSTR_B + coff;
                ldsm4(bh4, rb);
                ldsm4(bl4, rb + GTILE_B);
#pragma unroll
                for (int mi = 0; mi < 2; mi++) {
                    mma_bf16(acc[mi][2*g2],   ah[mi], bh4[0], bh4[2]);
                    mma_bf16(acc[mi][2*g2],   ah[mi], bl4[0], bl4[2]);
                    mma_bf16(acc[mi][2*g2],   al[mi], bh4[0], bh4[2]);
                    mma_bf16(acc[mi][2*g2+1], ah[mi], bh4[1], bh4[3]);
                    mma_bf16(acc[mi][2*g2+1], ah[mi], bl4[1], bl4[3]);
                    mma_bf16(acc[mi][2*g2+1], al[mi], bh4[1], bh4[3]);
                }
            }
        }
        __syncthreads();
    }

    // epilogue
    const int nb = n0 + wn * 64;               // 64-aligned: single (region, head)
    const int region = nb >> 10;
    const int h = (nb & 1023) >> 6;
    __nv_bfloat16* dh = region == 0 ? g_qh : region == 1 ? g_kh : g_vh;
    __nv_bfloat16* dl = region == 0 ? g_ql : region == 1 ? g_kl : g_vl;
    const float scale = (region == 0) ? 0.125f : 1.0f;

#pragma unroll
    for (int mi = 0; mi < 2; mi++) {
#pragma unroll
        for (int rr = 0; rr < 2; rr++) {
            const int m = m0 + wm * 32 + mi * 16 + (lane >> 2) + rr * 8;
            const int b = m >> 11, t = m & 2047;
            __nv_bfloat16* rh = dh + (((size_t)b * HEADS + h) * TSEQ + t) * HD;
            __nv_bfloat16* rl = dl + (((size_t)b * HEADS + h) * TSEQ + t) * HD;
#pragma unroll
            for (int nj = 0; nj < 8; nj++) {
                const int d = nj * 8 + 2 * (lane & 3);
                float2 bv = *(const float2*)(bias + nb + d);
                float v0 = (acc[mi][nj][rr*2+0] + bv.x) * scale;
                float v1 = (acc[mi][nj][rr*2+1] + bv.y) * scale;
                __nv_bfloat16 h0 = __float2bfloat16(v0), h1 = __float2bfloat16(v1);
                float r0 = v0 - __bfloat162float(h0);
                float r1 = v1 - __bfloat162float(h1);
                *(__nv_bfloat162*)(rh + d) = __nv_bfloat162(h0, h1);
                *(__nv_bfloat162*)(rl + d) =
                    __nv_bfloat162(__float2bfloat16(r0), __float2bfloat16(r1));
            }
        }
    }
}

// ---------------------------------------------------------------------------
// Kernel 2: flash attention via mma.sync bf16x3.
// CTA = 128 q-rows x (64 k-cols per iter); 8 warps of 16 q-rows.
// Q fragments register-resident; S acc reused in-register as P A-frags.
// ---------------------------------------------------------------------------
#define ASTR_B   144                // bytes per smem row (64 bf16 + pad)
#define QTILE_B  (128*ASTR_B)       // 18432
#define KTILE_B  (64*ASTR_B)        // 9216
#define ABUF0    (2*QTILE_B)        // 36864: start of KV buffers
#define ABUF_B   (4*KTILE_B)        // 36864 per buffer

__device__ __forceinline__ void kv_load(uint32_t sbase, int tid, size_t krow0,
                                        int kb, int buf)
{
#pragma unroll
    for (int i = 0; i < 8; i++) {
        const int arr = i >> 1;                // 0 kh, 1 kl, 2 vh, 3 vl
        int rem = ((i & 1) << 8) + tid;        // 0..511
        int row = rem >> 3, q = rem & 7;
        const __nv_bfloat16* g =
            (arr == 0 ? g_kh : arr == 1 ? g_kl : arr == 2 ? g_vh : g_vl) +
            (krow0 + (size_t)kb * 64 + row) * HD + q * 8;
        CP_ASYNC(sbase + ABUF0 + buf * ABUF_B + arr * KTILE_B + row * ASTR_B + q * 16, g);
    }
}

__global__ __launch_bounds__(256, 1) void attn_mma(float* __restrict__ out)
{
    extern __shared__ char sma[];
    const uint32_t sbase = smem_to_u32(sma);
    const int tid = threadIdx.x, lane = tid & 31, wid = tid >> 5;
    const int qbi = gridDim.x - 1 - blockIdx.x;   // longest CTAs first
    const int bh = blockIdx.y;
    const int kmax = 2 * qbi + 2;
    const size_t qrow0 = (size_t)bh * TSEQ + (size_t)qbi * 128;
    const size_t krow0 = (size_t)bh * TSEQ;

    // Q tiles (hi/lo) -> smem
#pragma unroll
    for (int i = 0; i < 8; i++) {
        const int arr = i >> 2;                 // 0 qh, 1 ql
        int rem = ((i & 3) << 8) + tid;         // 0..1023
        int row = rem >> 3, q = rem & 7;
        const __nv_bfloat16* g = (arr ? g_ql : g_qh) + (qrow0 + row) * HD + q * 8;
        CP_ASYNC(sbase + arr * QTILE_B + row * ASTR_B + q * 16, g);
    }
    CP_COMMIT();
    kv_load(sbase, tid, krow0, 0, 0);
    CP_COMMIT();
    CP_WAIT1();                                  // Q arrived
    __syncthreads();

    // Q fragments, register-resident
    uint32_t qfh[4][4], qfl[4][4];
#pragma unroll
    for (int ks = 0; ks < 4; ks++) {
        uint32_t a = sbase + (wid * 16 + (lane & 15)) * ASTR_B +
                     (ks * 16 + ((lane >> 4) << 3)) * 2;
        ldsm4(qfh[ks], a);
        ldsm4(qfl[ks], a + QTILE_B);
    }

    float o[8][4];
#pragma unroll
    for (int nj = 0; nj < 8; nj++)
#pragma unroll
        for (int c = 0; c < 4; c++) o[nj][c] = 0.f;
    float m1 = -1e30f, m2 = -1e30f, l1 = 0.f, l2 = 0.f;

    for (int kb = 0; kb < kmax; kb++) {
        const int buf = kb & 1;
        if (kb + 1 < kmax) {
            kv_load(sbase, tid, krow0, kb + 1, buf ^ 1);
            CP_COMMIT();
            CP_WAIT1();
        } else {
            CP_WAIT0();
        }
        __syncthreads();

        const bool active = (kb * 64 <= qbi * 128 + wid * 16 + 15);
        if (active) {
            // ---- S = Q K^T (split bf16, 3 MMAs) ----
            float s[8][4];
#pragma unroll
            for (int nj = 0; nj < 8; nj++)
#pragma unroll
                for (int c = 0; c < 4; c++) s[nj][c] = 0.f;

            const uint32_t kbase = sbase + ABUF0 + buf * ABUF_B;
#pragma unroll
            for (int ks = 0; ks < 4; ks++) {
                const uint32_t coff = (ks * 16 + ((lane >> 4) << 3)) * 2;
#pragma unroll
                for (int g2 = 0; g2 < 4; g2++) {
                    uint32_t bh4[4], bl4[4];
                    uint32_t rb = kbase + (g2 * 16 + (lane & 15)) * ASTR_B + coff;
                    ldsm4(bh4, rb);
                    ldsm4(bl4, rb + KTILE_B);
                    mma_bf16(s[2*g2],   qfh[ks], bh4[0], bh4[2]);
                    mma_bf16(s[2*g2],   qfh[ks], bl4[0], bl4[2]);
                    mma_bf16(s[2*g2],   qfl[ks], bh4[0], bh4[2]);
                    mma_bf16(s[2*g2+1], qfh[ks], bh4[1], bh4[3]);
                    mma_bf16(s[2*g2+1], qfh[ks], bl4[1], bl4[3]);
                    mma_bf16(s[2*g2+1], qfl[ks], bh4[1], bh4[3]);
                }
            }

            // ---- causal mask (diagonal blocks only) ----
            if (kb >= 2 * qbi) {
                const int q1 = qbi * 128 + wid * 16 + (lane >> 2);
                const int tb = kb * 64 + 2 * (lane & 3);
#pragma unroll
                for (int nj = 0; nj < 8; nj++) {
                    const int t0 = tb + 8 * nj;
                    if (t0     > q1)     s[nj][0] = -1e30f;
                    if (t0 + 1 > q1)     s[nj][1] = -1e30f;
                    if (t0     > q1 + 8) s[nj][2] = -1e30f;
                    if (t0 + 1 > q1 + 8) s[nj][3] = -1e30f;
                }
            }

            // ---- online softmax (rows r1=lane/4, r2=r1+8) ----
            float mx1 = -1e30f, mx2 = -1e30f;
#pragma unroll
            for (int nj = 0; nj < 8; nj++) {
                mx1 = fmaxf(mx1, fmaxf(s[nj][0], s[nj][1]));
                mx2 = fmaxf(mx2, fmaxf(s[nj][2], s[nj][3]));
            }
            mx1 = fmaxf(mx1, __shfl_xor_sync(0xffffffffu, mx1, 1));
            mx1 = fmaxf(mx1, __shfl_xor_sync(0xffffffffu, mx1, 2));
            mx2 = fmaxf(mx2, __shfl_xor_sync(0xffffffffu, mx2, 1));
            mx2 = fmaxf(mx2, __shfl_xor_sync(0xffffffffu, mx2, 2));
            const float mn1 = fmaxf(m1, mx1), mn2 = fmaxf(m2, mx2);
            const float a1 = __expf(m1 - mn1), a2 = __expf(m2 - mn2);
            float rs1 = 0.f, rs2 = 0.f;
#pragma unroll
            for (int nj = 0; nj < 8; nj++) {
                s[nj][0] = __expf(s[nj][0] - mn1);
                s[nj][1] = __expf(s[nj][1] - mn1);
                s[nj][2] = __expf(s[nj][2] - mn2);
                s[nj][3] = __expf(s[nj][3] - mn2);
                rs1 += s[nj][0] + s[nj][1];
                rs2 += s[nj][2] + s[nj][3];
            }
            rs1 += __shfl_xor_sync(0xffffffffu, rs1, 1);
            rs1 += __shfl_xor_sync(0xffffffffu, rs1, 2);
            rs2 += __shfl_xor_sync(0xffffffffu, rs2, 1);
            rs2 += __shfl_xor_sync(0xffffffffu, rs2, 2);
            l1 = l1 * a1 + rs1;  l2 = l2 * a2 + rs2;
            m1 = mn1;            m2 = mn2;
#pragma unroll
            for (int nj = 0; nj < 8; nj++) {
                o[nj][0] *= a1; o[nj][1] *= a1;
                o[nj][2] *= a2; o[nj][3] *= a2;
            }

            // ---- O += P V (split bf16, 3 MMAs) ----
            const uint32_t vbase = kbase + 2 * KTILE_B;
#pragma unroll
            for (int kt = 0; kt < 4; kt++) {
                uint32_t ph[4], pl[4];
#pragma unroll
                for (int half = 0; half < 2; half++) {
                    const float* p = s[2 * kt + half];
                    __nv_bfloat16 h0 = __float2bfloat16(p[0]);
                    __nv_bfloat16 h1 = __float2bfloat16(p[1]);
                    __nv_bfloat16 h2 = __float2bfloat16(p[2]);
                    __nv_bfloat16 h3 = __float2bfloat16(p[3]);
                    ph[2*half+0] = pack2(h0, h1);
                    ph[2*half+1] = pack2(h2, h3);
                    pl[2*half+0] = pack2(__float2bfloat16(p[0] - __bfloat162float(h0)),
                                         __float2bfloat16(p[1] - __bfloat162float(h1)));
                    pl[2*half+1] = pack2(__float2bfloat16(p[2] - __bfloat162float(h2)),
                                         __float2bfloat16(p[3] - __bfloat162float(h3)));
                }
#pragma unroll
                for (int g2 = 0; g2 < 4; g2++) {
                    uint32_t vh4[4], vl4[4];
                    uint32_t rb = vbase + (kt * 16 + (lane & 15)) * ASTR_B +
                                  (g2 * 16 + ((lane >> 4) << 3)) * 2;
                    ldsm4t(vh4, rb);
                    ldsm4t(vl4, rb + KTILE_B);
                    mma_bf16(o[2*g2],   ph, vh4[0], vh4[1]);
                    mma_bf16(o[2*g2],   ph, vl4[0], vl4[1]);
                    mma_bf16(o[2*g2],   pl, vh4[0], vh4[1]);
                    mma_bf16(o[2*g2+1], ph, vh4[2], vh4[3]);
                    mma_bf16(o[2*g2+1], ph, vl4[2], vl4[3]);
                    mma_bf16(o[2*g2+1], pl, vh4[2], vh4[3]);
                }
            }
        }
        __syncthreads();
    }

    // epilogue: out[b][t][h*64+d] = o / l
    const float inv1 = 1.f / l1, inv2 = 1.f / l2;
    const int b = bh >> 4, h = bh & 15;
    const int t1 = qbi * 128 + wid * 16 + (lane >> 2);
    float* o1p = out + ((size_t)b * TSEQ + t1) * CDIM + h * 64 + 2 * (lane & 3);
    float* o2p = o1p + (size_t)8 * CDIM;
#pragma unroll
    for (int nj = 0; nj < 8; nj++) {
        *(float2*)(o1p + 8 * nj) = make_float2(o[nj][0] * inv1, o[nj][1] * inv1);
        *(float2*)(o2p + 8 * nj) = make_float2(o[nj][2] * inv2, o[nj][3] * inv2);
    }
}

// ---------------------------------------------------------------------------
extern "C" void kernel_launch(void* const* d_in, const int* in_sizes, int n_in,
                              void* d_out, int out_size)
{
    (void)in_sizes; (void)n_in; (void)out_size;
    const float* x  = (const float*)d_in[0];
    const float* w  = (const float*)d_in[1];
    const float* bb = (const float*)d_in[2];
    float* out = (float*)d_out;

    __nv_bfloat16 *xh, *xl, *wh, *wl;
    cudaGetSymbolAddress((void**)&xh, g_xh);
    cudaGetSymbolAddress((void**)&xl, g_xl);
    cudaGetSymbolAddress((void**)&wh, g_wh);
    cudaGetSymbolAddress((void**)&wl, g_wl);

    const int nx4 = BT * CDIM / 4;
    const int nw4 = NQKV * CDIM / 4;
    split_bf16<<<(nx4 + 255) / 256, 256>>>(x, xh, xl, nx4);
    split_bf16<<<(nw4 + 255) / 256, 256>>>(w, wh, wl, nw4);

    const int gsmem = 2 * GBUF_B;                       // 81920
    cudaFuncSetAttribute((const void*)qkv_gemm_mma,
                         cudaFuncAttributeMaxDynamicSharedMemorySize, gsmem);
    dim3 gg(NQKV / 128, BT / 128);                      // (24, 64)
    qkv_gemm_mma<<<gg, 256, gsmem>>>(bb);

    const int asmem = ABUF0 + 2 * ABUF_B;               // 110592
    cudaFuncSetAttribute((const void*)attn_mma,
                         cudaFuncAttributeMaxDynamicSharedMemorySize, asmem);
    dim3 ga(TSEQ / 128, NB * HEADS);                    // (16, 64)
    attn_mma<<<ga, 256, asmem>>>(out);
}

// round 4
// speedup vs baseline: 3.4518x; 1.1254x over previous
#include <cuda_runtime.h>
#include <cuda_bf16.h>
#include <cuda_fp16.h>
#include <cstdint>

#define NB    4
#define TSEQ  2048
#define CDIM  1024
#define HEADS 16
#define HD    64
#define BT    (NB*TSEQ)          // 8192
#define NQKV  3072

// Q pre-scale: 1/sqrt(64) * log2(e)  (softmax done in base-2 domain)
#define QSCALE (0.125f * 1.44269504088896f)

// ---------------------------------------------------------------------------
// __device__ global scratch (no runtime allocation)
// ---------------------------------------------------------------------------
__device__ __nv_bfloat16 g_xh[(size_t)BT*CDIM];
__device__ __nv_bfloat16 g_xl[(size_t)BT*CDIM];
__device__ __nv_bfloat16 g_wh[(size_t)NQKV*CDIM];
__device__ __nv_bfloat16 g_wl[(size_t)NQKV*CDIM];
// Q/K hi/lo fp16 pairs, V hi fp16, all [B,H,T,D]
__device__ __half g_qh[(size_t)NB*HEADS*TSEQ*HD];
__device__ __half g_ql[(size_t)NB*HEADS*TSEQ*HD];
__device__ __half g_kh[(size_t)NB*HEADS*TSEQ*HD];
__device__ __half g_kl[(size_t)NB*HEADS*TSEQ*HD];
__device__ __half g_vh[(size_t)NB*HEADS*TSEQ*HD];

// ---------------------------------------------------------------------------
// Helpers (sm_80-class ISA: mma.sync / ldmatrix / cp.async)
// ---------------------------------------------------------------------------
__device__ __forceinline__ uint32_t smem_to_u32(const void* p) {
    uint32_t a;
    asm("{ .reg .u64 t; cvta.to.shared.u64 t, %1; cvt.u32.u64 %0, t; }" : "=r"(a) : "l"(p));
    return a;
}
#define CP_ASYNC(dst, src) \
    asm volatile("cp.async.cg.shared.global [%0], [%1], 16;\n" :: "r"(dst), "l"(src))
#define CP_COMMIT() asm volatile("cp.async.commit_group;\n" ::: "memory")
#define CP_WAIT1()  asm volatile("cp.async.wait_group 1;\n" ::: "memory")
#define CP_WAIT0()  asm volatile("cp.async.wait_group 0;\n" ::: "memory")

__device__ __forceinline__ void ldsm4(uint32_t r[4], uint32_t a) {
    asm volatile("ldmatrix.sync.aligned.m8n8.x4.shared.b16 {%0,%1,%2,%3}, [%4];"
                 : "=r"(r[0]), "=r"(r[1]), "=r"(r[2]), "=r"(r[3]) : "r"(a));
}
__device__ __forceinline__ void ldsm4t(uint32_t r[4], uint32_t a) {
    asm volatile("ldmatrix.sync.aligned.m8n8.x4.trans.shared.b16 {%0,%1,%2,%3}, [%4];"
                 : "=r"(r[0]), "=r"(r[1]), "=r"(r[2]), "=r"(r[3]) : "r"(a));
}
__device__ __forceinline__ void mma_bf16(float c[4], const uint32_t a[4],
                                         uint32_t b0, uint32_t b1) {
    asm volatile("mma.sync.aligned.m16n8k16.row.col.f32.bf16.bf16.f32 "
                 "{%0,%1,%2,%3}, {%4,%5,%6,%7}, {%8,%9}, {%0,%1,%2,%3};"
                 : "+f"(c[0]), "+f"(c[1]), "+f"(c[2]), "+f"(c[3])
                 : "r"(a[0]), "r"(a[1]), "r"(a[2]), "r"(a[3]), "r"(b0), "r"(b1));
}
__device__ __forceinline__ void mma_f16(float c[4], const uint32_t a[4],
                                        uint32_t b0, uint32_t b1) {
    asm volatile("mma.sync.aligned.m16n8k16.row.col.f32.f16.f16.f32 "
                 "{%0,%1,%2,%3}, {%4,%5,%6,%7}, {%8,%9}, {%0,%1,%2,%3};"
                 : "+f"(c[0]), "+f"(c[1]), "+f"(c[2]), "+f"(c[3])
                 : "r"(a[0]), "r"(a[1]), "r"(a[2]), "r"(a[3]), "r"(b0), "r"(b1));
}
__device__ __forceinline__ uint32_t pack2h(__half a, __half b) {
    __half2 t(a, b);
    return *reinterpret_cast<uint32_t*>(&t);
}

// ---------------------------------------------------------------------------
// Kernel 0: split fp32 -> bf16 hi/lo (GEMM inputs)
// ---------------------------------------------------------------------------
__global__ __launch_bounds__(256) void split_bf16(const float* __restrict__ src,
                                                  __nv_bfloat16* __restrict__ hi,
                                                  __nv_bfloat16* __restrict__ lo,
                                                  int n4)
{
    int i = blockIdx.x * 256 + threadIdx.x;
    if (i >= n4) return;
    float4 v = ((const float4*)src)[i];
    __nv_bfloat16 h0 = __float2bfloat16(v.x), h1 = __float2bfloat16(v.y);
    __nv_bfloat16 h2 = __float2bfloat16(v.z), h3 = __float2bfloat16(v.w);
    __nv_bfloat16 l0 = __float2bfloat16(v.x - __bfloat162float(h0));
    __nv_bfloat16 l1 = __float2bfloat16(v.y - __bfloat162float(h1));
    __nv_bfloat16 l2 = __float2bfloat16(v.z - __bfloat162float(h2));
    __nv_bfloat16 l3 = __float2bfloat16(v.w - __bfloat162float(h3));
    __nv_bfloat162* hp = (__nv_bfloat162*)hi;
    __nv_bfloat162* lp = (__nv_bfloat162*)lo;
    hp[2*i]   = __nv_bfloat162(h0, h1);
    hp[2*i+1] = __nv_bfloat162(h2, h3);
    lp[2*i]   = __nv_bfloat162(l0, l1);
    lp[2*i+1] = __nv_bfloat162(l2, l3);
}

// ---------------------------------------------------------------------------
// Kernel 1: QKV GEMM, bf16x3 mma.sync. CTA 128x128, 4 warps (64x64 each),
// KC=32 double-buffered cp.async, 2 CTAs/SM. Epilogue: +bias, Q-scale,
// fp16 hi/lo split, scatter to [B,H,T,D].
// ---------------------------------------------------------------------------
#define KCG      32
#define GSTR_B   80
#define GTILE_B  (128*GSTR_B)       // 10240
#define GSTAGE_B (4*GTILE_B)        // 40960

__device__ __forceinline__ void gemm_load(uint32_t sdst, int tid, int k0, int m0, int n0)
{
#pragma unroll
    for (int i = 0; i < 16; i++) {
        const int tile = i >> 2;                 // 0 xh, 1 xl, 2 wh, 3 wl
        int idx = ((i & 3) << 7) + tid;          // 0..511
        int row = idx >> 2, q = idx & 3;
        const __nv_bfloat16* g =
            (tile == 0) ? g_xh + (size_t)(m0 + row) * CDIM :
            (tile == 1) ? g_xl + (size_t)(m0 + row) * CDIM :
            (tile == 2) ? g_wh + (size_t)(n0 + row) * CDIM :
                          g_wl + (size_t)(n0 + row) * CDIM;
        CP_ASYNC(sdst + tile * GTILE_B + row * GSTR_B + q * 16, g + k0 + q * 8);
    }
}

__global__ __launch_bounds__(128, 2) void qkv_gemm_mma(const float* __restrict__ bias)
{
    extern __shared__ char smg[];
    const uint32_t sbase = smem_to_u32(smg);
    const int tid = threadIdx.x, lane = tid & 31, wid = tid >> 5;
    const int m0 = blockIdx.y * 128, n0 = blockIdx.x * 128;
    const int wm = wid & 1, wn = wid >> 1;

    float acc[4][8][4];
#pragma unroll
    for (int mi = 0; mi < 4; mi++)
#pragma unroll
        for (int nj = 0; nj < 8; nj++)
#pragma unroll
            for (int c = 0; c < 4; c++) acc[mi][nj][c] = 0.f;

    gemm_load(sbase, tid, 0, m0, n0);
    CP_COMMIT();

    const int NCH = CDIM / KCG;     // 32
    for (int c = 0; c < NCH; c++) {
        const int buf = c & 1;
        if (c + 1 < NCH) {
            gemm_load(sbase + (buf ^ 1) * GSTAGE_B, tid, (c + 1) * KCG, m0, n0);
            CP_COMMIT();
            CP_WAIT1();
        } else {
            CP_WAIT0();
        }
        __syncthreads();

        const uint32_t bb = sbase + buf * GSTAGE_B;
#pragma unroll
        for (int ks = 0; ks < 2; ks++) {
            const uint32_t coff = (ks * 16 + ((lane >> 4) << 3)) * 2;
            uint32_t ah[4][4], al[4][4];
#pragma unroll
            for (int mi = 0; mi < 4; mi++) {
                uint32_t ra = bb + (wm * 64 + mi * 16 + (lane & 15)) * GSTR_B + coff;
                ldsm4(ah[mi], ra);
                ldsm4(al[mi], ra + GTILE_B);
            }
#pragma unroll
            for (int g2 = 0; g2 < 4; g2++) {
                uint32_t bh4[4], bl4[4];
                uint32_t rb = bb + 2 * GTILE_B +
                              (wn * 64 + g2 * 16 + (lane & 15)) * GSTR_B + coff;
                ldsm4(bh4, rb);
                ldsm4(bl4, rb + GTILE_B);
#pragma unroll
                for (int mi = 0; mi < 4; mi++) {
                    mma_bf16(acc[mi][2*g2],   ah[mi], bh4[0], bh4[2]);
                    mma_bf16(acc[mi][2*g2],   ah[mi], bl4[0], bl4[2]);
                    mma_bf16(acc[mi][2*g2],   al[mi], bh4[0], bh4[2]);
                    mma_bf16(acc[mi][2*g2+1], ah[mi], bh4[1], bh4[3]);
                    mma_bf16(acc[mi][2*g2+1], ah[mi], bl4[1], bl4[3]);
                    mma_bf16(acc[mi][2*g2+1], al[mi], bh4[1], bh4[3]);
                }
            }
        }
        __syncthreads();
    }

    // epilogue: +bias, scale (Q only), fp16 hi/lo split, scatter
    const int nb = n0 + wn * 64;                 // 64-aligned: one (region, head)
    const int region = nb >> 10;
    const int h = (nb & 1023) >> 6;
    __half* dh = region == 0 ? g_qh : region == 1 ? g_kh : g_vh;
    __half* dl = region == 0 ? g_ql : g_kl;      // unused for region 2
    const bool has_lo = (region != 2);
    const float scale = (region == 0) ? QSCALE : 1.0f;

#pragma unroll
    for (int mi = 0; mi < 4; mi++) {
#pragma unroll
        for (int rr = 0; rr < 2; rr++) {
            const int m = m0 + wm * 64 + mi * 16 + (lane >> 2) + rr * 8;
            const int b = m >> 11, t = m & 2047;
            const size_t roff = (((size_t)b * HEADS + h) * TSEQ + t) * HD;
#pragma unroll
            for (int nj = 0; nj < 8; nj++) {
                const int d = nj * 8 + 2 * (lane & 3);
                float2 bv = *(const float2*)(bias + nb + d);
                float v0 = (acc[mi][nj][rr*2+0] + bv.x) * scale;
                float v1 = (acc[mi][nj][rr*2+1] + bv.y) * scale;
                __half h0 = __float2half(v0), h1 = __float2half(v1);
                *(__half2*)(dh + roff + d) = __half2(h0, h1);
                if (has_lo) {
                    float r0 = v0 - __half2float(h0);
                    float r1 = v1 - __half2float(h1);
                    *(__half2*)(dl + roff + d) =
                        __half2(__float2half(r0), __float2half(r1));
                }
            }
        }
    }
}

// ---------------------------------------------------------------------------
// Kernel 2: flash attention, fp16 mma.sync.
// S = QK^T with hi/lo x3 (error ~2^-22); P*V single fp16 MMA (~3e-4).
// Softmax in base-2 domain (Q pre-scaled by log2e/8).
// ---------------------------------------------------------------------------
#define ASTR_B   144                // 64 fp16 (128B) + 16B pad
#define QTILE_B  (128*ASTR_B)       // 18432
#define KTILE_B  (64*ASTR_B)        // 9216
#define ABUF0    (2*QTILE_B)        // 36864
#define ABUF_B   (3*KTILE_B)        // 27648 (kh, kl, vh)

__device__ __forceinline__ void kv_load(uint32_t sbase, int tid, size_t krow0,
                                        int kb, int buf)
{
#pragma unroll
    for (int i = 0; i < 6; i++) {
        const int arr = i >> 1;                // 0 kh, 1 kl, 2 vh
        int rem = ((i & 1) << 8) + tid;        // 0..511
        int row = rem >> 3, q = rem & 7;
        const __half* g = (arr == 0 ? g_kh : arr == 1 ? g_kl : g_vh) +
                          (krow0 + (size_t)kb * 64 + row) * HD + q * 8;
        CP_ASYNC(sbase + ABUF0 + buf * ABUF_B + arr * KTILE_B + row * ASTR_B + q * 16, g);
    }
}

__global__ __launch_bounds__(256, 1) void attn_mma(float* __restrict__ out)
{
    extern __shared__ char sma[];
    const uint32_t sbase = smem_to_u32(sma);
    const int tid = threadIdx.x, lane = tid & 31, wid = tid >> 5;
    const int qbi = gridDim.x - 1 - blockIdx.x;
    const int bh = blockIdx.y;
    const int kmax = 2 * qbi + 2;
    const size_t qrow0 = (size_t)bh * TSEQ + (size_t)qbi * 128;
    const size_t krow0 = (size_t)bh * TSEQ;

    // Q hi/lo -> smem
#pragma unroll
    for (int i = 0; i < 8; i++) {
        const int arr = i >> 2;                 // 0 qh, 1 ql
        int rem = ((i & 3) << 8) + tid;         // 0..1023
        int row = rem >> 3, q = rem & 7;
        const __half* g = (arr ? g_ql : g_qh) + (qrow0 + row) * HD + q * 8;
        CP_ASYNC(sbase + arr * QTILE_B + row * ASTR_B + q * 16, g);
    }
    CP_COMMIT();
    kv_load(sbase, tid, krow0, 0, 0);
    CP_COMMIT();
    CP_WAIT1();
    __syncthreads();

    uint32_t qfh[4][4], qfl[4][4];
#pragma unroll
    for (int ks = 0; ks < 4; ks++) {
        uint32_t a = sbase + (wid * 16 + (lane & 15)) * ASTR_B +
                     (ks * 16 + ((lane >> 4) << 3)) * 2;
        ldsm4(qfh[ks], a);
        ldsm4(qfl[ks], a + QTILE_B);
    }

    float o[8][4];
#pragma unroll
    for (int nj = 0; nj < 8; nj++)
#pragma unroll
        for (int c = 0; c < 4; c++) o[nj][c] = 0.f;
    float m1 = -1e30f, m2 = -1e30f, l1 = 0.f, l2 = 0.f;

    for (int kb = 0; kb < kmax; kb++) {
        const int buf = kb & 1;
        if (kb + 1 < kmax) {
            kv_load(sbase, tid, krow0, kb + 1, buf ^ 1);
            CP_COMMIT();
            CP_WAIT1();
        } else {
            CP_WAIT0();
        }
        __syncthreads();

        const bool active = (kb * 64 <= qbi * 128 + wid * 16 + 15);
        if (active) {
            // ---- S = Q K^T (fp16 hi/lo, 3 MMAs) ----
            float s[8][4];
#pragma unroll
            for (int nj = 0; nj < 8; nj++)
#pragma unroll
                for (int c = 0; c < 4; c++) s[nj][c] = 0.f;

            const uint32_t kbase = sbase + ABUF0 + buf * ABUF_B;
#pragma unroll
            for (int ks = 0; ks < 4; ks++) {
                const uint32_t coff = (ks * 16 + ((lane >> 4) << 3)) * 2;
#pragma unroll
                for (int g2 = 0; g2 < 4; g2++) {
                    uint32_t bh4[4], bl4[4];
                    uint32_t rb = kbase + (g2 * 16 + (lane & 15)) * ASTR_B + coff;
                    ldsm4(bh4, rb);
                    ldsm4(bl4, rb + KTILE_B);
                    mma_f16(s[2*g2],   qfh[ks], bh4[0], bh4[2]);
                    mma_f16(s[2*g2],   qfh[ks], bl4[0], bl4[2]);
                    mma_f16(s[2*g2],   qfl[ks], bh4[0], bh4[2]);
                    mma_f16(s[2*g2+1], qfh[ks], bh4[1], bh4[3]);
                    mma_f16(s[2*g2+1], qfh[ks], bl4[1], bl4[3]);
                    mma_f16(s[2*g2+1], qfl[ks], bh4[1], bh4[3]);
                }
            }

            // ---- causal mask (diagonal 128-row band) ----
            if (kb >= 2 * qbi) {
                const int q1 = qbi * 128 + wid * 16 + (lane >> 2);
                const int tb = kb * 64 + 2 * (lane & 3);
#pragma unroll
                for (int nj = 0; nj < 8; nj++) {
                    const int t0 = tb + 8 * nj;
                    if (t0     > q1)     s[nj][0] = -1e30f;
                    if (t0 + 1 > q1)     s[nj][1] = -1e30f;
                    if (t0     > q1 + 8) s[nj][2] = -1e30f;
                    if (t0 + 1 > q1 + 8) s[nj][3] = -1e30f;
                }
            }

            // ---- online softmax, base-2 domain ----
            float mx1 = -1e30f, mx2 = -1e30f;
#pragma unroll
            for (int nj = 0; nj < 8; nj++) {
                mx1 = fmaxf(mx1, fmaxf(s[nj][0], s[nj][1]));
                mx2 = fmaxf(mx2, fmaxf(s[nj][2], s[nj][3]));
            }
            mx1 = fmaxf(mx1, __shfl_xor_sync(0xffffffffu, mx1, 1));
            mx1 = fmaxf(mx1, __shfl_xor_sync(0xffffffffu, mx1, 2));
            mx2 = fmaxf(mx2, __shfl_xor_sync(0xffffffffu, mx2, 1));
            mx2 = fmaxf(mx2, __shfl_xor_sync(0xffffffffu, mx2, 2));
            const float mn1 = fmaxf(m1, mx1), mn2 = fmaxf(m2, mx2);
            const float a1 = exp2f(m1 - mn1), a2 = exp2f(m2 - mn2);
            float rs1 = 0.f, rs2 = 0.f;
#pragma unroll
            for (int nj = 0; nj < 8; nj++) {
                s[nj][0] = exp2f(s[nj][0] - mn1);
                s[nj][1] = exp2f(s[nj][1] - mn1);
                s[nj][2] = exp2f(s[nj][2] - mn2);
                s[nj][3] = exp2f(s[nj][3] - mn2);
                rs1 += s[nj][0] + s[nj][1];
                rs2 += s[nj][2] + s[nj][3];
            }
            rs1 += __shfl_xor_sync(0xffffffffu, rs1, 1);
            rs1 += __shfl_xor_sync(0xffffffffu, rs1, 2);
            rs2 += __shfl_xor_sync(0xffffffffu, rs2, 1);
            rs2 += __shfl_xor_sync(0xffffffffu, rs2, 2);
            l1 = l1 * a1 + rs1;  l2 = l2 * a2 + rs2;
            m1 = mn1;            m2 = mn2;
#pragma unroll
            for (int nj = 0; nj < 8; nj++) {
                o[nj][0] *= a1; o[nj][1] *= a1;
                o[nj][2] *= a2; o[nj][3] *= a2;
            }

            // ---- O += P V (single fp16 MMA) ----
            const uint32_t vbase = kbase + 2 * KTILE_B;
#pragma unroll
            for (int kt = 0; kt < 4; kt++) {
                uint32_t ph[4];
                {
                    const float* p0 = s[2 * kt];
                    const float* p1 = s[2 * kt + 1];
                    ph[0] = pack2h(__float2half(p0[0]), __float2half(p0[1]));
                    ph[1] = pack2h(__float2half(p0[2]), __float2half(p0[3]));
                    ph[2] = pack2h(__float2half(p1[0]), __float2half(p1[1]));
                    ph[3] = pack2h(__float2half(p1[2]), __float2half(p1[3]));
                }
#pragma unroll
                for (int g2 = 0; g2 < 4; g2++) {
                    uint32_t vh4[4];
                    uint32_t rb = vbase + (kt * 16 + (lane & 15)) * ASTR_B +
                                  (g2 * 16 + ((lane >> 4) << 3)) * 2;
                    ldsm4t(vh4, rb);
                    mma_f16(o[2*g2],   ph, vh4[0], vh4[1]);
                    mma_f16(o[2*g2+1], ph, vh4[2], vh4[3]);
                }
            }
        }
        __syncthreads();
    }

    // epilogue
    const float inv1 = 1.f / l1, inv2 = 1.f / l2;
    const int b = bh >> 4, h = bh & 15;
    const int t1 = qbi * 128 + wid * 16 + (lane >> 2);
    float* o1p = out + ((size_t)b * TSEQ + t1) * CDIM + h * 64 + 2 * (lane & 3);
    float* o2p = o1p + (size_t)8 * CDIM;
#pragma unroll
    for (int nj = 0; nj < 8; nj++) {
        *(float2*)(o1p + 8 * nj) = make_float2(o[nj][0] * inv1, o[nj][1] * inv1);
        *(float2*)(o2p + 8 * nj) = make_float2(o[nj][2] * inv2, o[nj][3] * inv2);
    }
}

// ---------------------------------------------------------------------------
extern "C" void kernel_launch(void* const* d_in, const int* in_sizes, int n_in,
                              void* d_out, int out_size)
{
    (void)in_sizes; (void)n_in; (void)out_size;
    const float* x  = (const float*)d_in[0];
    const float* w  = (const float*)d_in[1];
    const float* bb = (const float*)d_in[2];
    float* out = (float*)d_out;

    __nv_bfloat16 *xh, *xl, *wh, *wl;
    cudaGetSymbolAddress((void**)&xh, g_xh);
    cudaGetSymbolAddress((void**)&xl, g_xl);
    cudaGetSymbolAddress((void**)&wh, g_wh);
    cudaGetSymbolAddress((void**)&wl, g_wl);

    const int nx4 = BT * CDIM / 4;
    const int nw4 = NQKV * CDIM / 4;
    split_bf16<<<(nx4 + 255) / 256, 256>>>(x, xh, xl, nx4);
    split_bf16<<<(nw4 + 255) / 256, 256>>>(w, wh, wl, nw4);

    const int gsmem = 2 * GSTAGE_B;                     // 81920
    cudaFuncSetAttribute((const void*)qkv_gemm_mma,
                         cudaFuncAttributeMaxDynamicSharedMemorySize, gsmem);
    dim3 gg(NQKV / 128, BT / 128);                      // (24, 64)
    qkv_gemm_mma<<<gg, 128, gsmem>>>(bb);

    const int asmem = ABUF0 + 2 * ABUF_B;               // 92160
    cudaFuncSetAttribute((const void*)attn_mma,
                         cudaFuncAttributeMaxDynamicSharedMemorySize, asmem);
    dim3 ga(TSEQ / 128, NB * HEADS);                    // (16, 64)
    attn_mma<<<ga, 256, asmem>>>(out);
}

// round 5
// speedup vs baseline: 3.5920x; 1.0406x over previous
#include <cuda_runtime.h>
#include <cuda_bf16.h>
#include <cuda_fp16.h>
#include <cstdint>

#define NB    4
#define TSEQ  2048
#define CDIM  1024
#define HEADS 16
#define HD    64
#define BT    (NB*TSEQ)          // 8192
#define NQKV  3072

// Q pre-scale: 1/sqrt(64) * log2(e)  (softmax in base-2 domain)
#define QSCALE (0.125f * 1.44269504088896f)

// ---------------------------------------------------------------------------
// __device__ global scratch
// ---------------------------------------------------------------------------
__device__ __nv_bfloat16 g_xh[(size_t)BT*CDIM];
__device__ __nv_bfloat16 g_xl[(size_t)BT*CDIM];
__device__ __nv_bfloat16 g_wh[(size_t)NQKV*CDIM];
__device__ __nv_bfloat16 g_wl[(size_t)NQKV*CDIM];
// Q fp16 (scaled), K hi/lo fp16, V fp16 — all [B,H,T,D]
__device__ __half g_qh[(size_t)NB*HEADS*TSEQ*HD];
__device__ __half g_kh[(size_t)NB*HEADS*TSEQ*HD];
__device__ __half g_kl[(size_t)NB*HEADS*TSEQ*HD];
__device__ __half g_vh[(size_t)NB*HEADS*TSEQ*HD];

// ---------------------------------------------------------------------------
// Helpers
// ---------------------------------------------------------------------------
__device__ __forceinline__ uint32_t smem_to_u32(const void* p) {
    uint32_t a;
    asm("{ .reg .u64 t; cvta.to.shared.u64 t, %1; cvt.u32.u64 %0, t; }" : "=r"(a) : "l"(p));
    return a;
}
#define CP_ASYNC(dst, src) \
    asm volatile("cp.async.cg.shared.global [%0], [%1], 16;\n" :: "r"(dst), "l"(src))
#define CP_COMMIT() asm volatile("cp.async.commit_group;\n" ::: "memory")
#define CP_WAIT1()  asm volatile("cp.async.wait_group 1;\n" ::: "memory")
#define CP_WAIT0()  asm volatile("cp.async.wait_group 0;\n" ::: "memory")

__device__ __forceinline__ void ldsm4(uint32_t r[4], uint32_t a) {
    asm volatile("ldmatrix.sync.aligned.m8n8.x4.shared.b16 {%0,%1,%2,%3}, [%4];"
                 : "=r"(r[0]), "=r"(r[1]), "=r"(r[2]), "=r"(r[3]) : "r"(a));
}
__device__ __forceinline__ void ldsm4t(uint32_t r[4], uint32_t a) {
    asm volatile("ldmatrix.sync.aligned.m8n8.x4.trans.shared.b16 {%0,%1,%2,%3}, [%4];"
                 : "=r"(r[0]), "=r"(r[1]), "=r"(r[2]), "=r"(r[3]) : "r"(a));
}
__device__ __forceinline__ void mma_bf16(float c[4], const uint32_t a[4],
                                         uint32_t b0, uint32_t b1) {
    asm volatile("mma.sync.aligned.m16n8k16.row.col.f32.bf16.bf16.f32 "
                 "{%0,%1,%2,%3}, {%4,%5,%6,%7}, {%8,%9}, {%0,%1,%2,%3};"
                 : "+f"(c[0]), "+f"(c[1]), "+f"(c[2]), "+f"(c[3])
                 : "r"(a[0]), "r"(a[1]), "r"(a[2]), "r"(a[3]), "r"(b0), "r"(b1));
}
__device__ __forceinline__ void mma_f16(float c[4], const uint32_t a[4],
                                        uint32_t b0, uint32_t b1) {
    asm volatile("mma.sync.aligned.m16n8k16.row.col.f32.f16.f16.f32 "
                 "{%0,%1,%2,%3}, {%4,%5,%6,%7}, {%8,%9}, {%0,%1,%2,%3};"
                 : "+f"(c[0]), "+f"(c[1]), "+f"(c[2]), "+f"(c[3])
                 : "r"(a[0]), "r"(a[1]), "r"(a[2]), "r"(a[3]), "r"(b0), "r"(b1));
}
__device__ __forceinline__ uint32_t pack2h(__half a, __half b) {
    __half2 t(a, b);
    return *reinterpret_cast<uint32_t*>(&t);
}

// ---------------------------------------------------------------------------
// Kernel 0: split fp32 -> bf16 hi/lo
// ---------------------------------------------------------------------------
__global__ __launch_bounds__(256) void split_bf16(const float* __restrict__ src,
                                                  __nv_bfloat16* __restrict__ hi,
                                                  __nv_bfloat16* __restrict__ lo,
                                                  int n4)
{
    int i = blockIdx.x * 256 + threadIdx.x;
    if (i >= n4) return;
    float4 v = ((const float4*)src)[i];
    __nv_bfloat16 h0 = __float2bfloat16(v.x), h1 = __float2bfloat16(v.y);
    __nv_bfloat16 h2 = __float2bfloat16(v.z), h3 = __float2bfloat16(v.w);
    __nv_bfloat16 l0 = __float2bfloat16(v.x - __bfloat162float(h0));
    __nv_bfloat16 l1 = __float2bfloat16(v.y - __bfloat162float(h1));
    __nv_bfloat16 l2 = __float2bfloat16(v.z - __bfloat162float(h2));
    __nv_bfloat16 l3 = __float2bfloat16(v.w - __bfloat162float(h3));
    __nv_bfloat162* hp = (__nv_bfloat162*)hi;
    __nv_bfloat162* lp = (__nv_bfloat162*)lo;
    hp[2*i]   = __nv_bfloat162(h0, h1);
    hp[2*i+1] = __nv_bfloat162(h2, h3);
    lp[2*i]   = __nv_bfloat162(l0, l1);
    lp[2*i+1] = __nv_bfloat162(l2, l3);
}

// ---------------------------------------------------------------------------
// Kernel 1: QKV GEMM, bf16x3 mma.sync, term-major MMA order (acc reuse
// distance 8). CTA 128x128, 4 warps (64x64), KC=32 double-buffered.
// ---------------------------------------------------------------------------
#define KCG      32
#define GSTR_B   80
#define GTILE_B  (128*GSTR_B)       // 10240
#define GSTAGE_B (4*GTILE_B)        // 40960

__device__ __forceinline__ void gemm_load(uint32_t sdst, int tid, int k0, int m0, int n0)
{
#pragma unroll
    for (int i = 0; i < 16; i++) {
        const int tile = i >> 2;                 // 0 xh, 1 xl, 2 wh, 3 wl
        int idx = ((i & 3) << 7) + tid;          // 0..511
        int row = idx >> 2, q = idx & 3;
        const __nv_bfloat16* g =
            (tile == 0) ? g_xh + (size_t)(m0 + row) * CDIM :
            (tile == 1) ? g_xl + (size_t)(m0 + row) * CDIM :
            (tile == 2) ? g_wh + (size_t)(n0 + row) * CDIM :
                          g_wl + (size_t)(n0 + row) * CDIM;
        CP_ASYNC(sdst + tile * GTILE_B + row * GSTR_B + q * 16, g + k0 + q * 8);
    }
}

__global__ __launch_bounds__(128, 2) void qkv_gemm_mma(const float* __restrict__ bias)
{
    extern __shared__ char smg[];
    const uint32_t sbase = smem_to_u32(smg);
    const int tid = threadIdx.x, lane = tid & 31, wid = tid >> 5;
    const int m0 = blockIdx.y * 128, n0 = blockIdx.x * 128;
    const int wm = wid & 1, wn = wid >> 1;

    float acc[4][8][4];
#pragma unroll
    for (int mi = 0; mi < 4; mi++)
#pragma unroll
        for (int nj = 0; nj < 8; nj++)
#pragma unroll
            for (int c = 0; c < 4; c++) acc[mi][nj][c] = 0.f;

    gemm_load(sbase, tid, 0, m0, n0);
    CP_COMMIT();

    const int NCH = CDIM / KCG;     // 32
    for (int c = 0; c < NCH; c++) {
        const int buf = c & 1;
        if (c + 1 < NCH) {
            gemm_load(sbase + (buf ^ 1) * GSTAGE_B, tid, (c + 1) * KCG, m0, n0);
            CP_COMMIT();
            CP_WAIT1();
        } else {
            CP_WAIT0();
        }
        __syncthreads();

        const uint32_t bb = sbase + buf * GSTAGE_B;
#pragma unroll
        for (int ks = 0; ks < 2; ks++) {
            const uint32_t coff = (ks * 16 + ((lane >> 4) << 3)) * 2;
            uint32_t ah[4][4], al[4][4];
#pragma unroll
            for (int mi = 0; mi < 4; mi++) {
                uint32_t ra = bb + (wm * 64 + mi * 16 + (lane & 15)) * GSTR_B + coff;
                ldsm4(ah[mi], ra);
                ldsm4(al[mi], ra + GTILE_B);
            }
#pragma unroll
            for (int g2 = 0; g2 < 4; g2++) {
                uint32_t bh4[4], bl4[4];
                uint32_t rb = bb + 2 * GTILE_B +
                              (wn * 64 + g2 * 16 + (lane & 15)) * GSTR_B + coff;
                ldsm4(bh4, rb);
                ldsm4(bl4, rb + GTILE_B);
                // term-major: 8 distinct accumulators between reuses
#pragma unroll
                for (int mi = 0; mi < 4; mi++) {
                    mma_bf16(acc[mi][2*g2],   ah[mi], bh4[0], bh4[2]);
                    mma_bf16(acc[mi][2*g2+1], ah[mi], bh4[1], bh4[3]);
                }
#pragma unroll
                for (int mi = 0; mi < 4; mi++) {
                    mma_bf16(acc[mi][2*g2],   ah[mi], bl4[0], bl4[2]);
                    mma_bf16(acc[mi][2*g2+1], ah[mi], bl4[1], bl4[3]);
                }
#pragma unroll
                for (int mi = 0; mi < 4; mi++) {
                    mma_bf16(acc[mi][2*g2],   al[mi], bh4[0], bh4[2]);
                    mma_bf16(acc[mi][2*g2+1], al[mi], bh4[1], bh4[3]);
                }
            }
        }
        __syncthreads();
    }

    // epilogue: +bias; Q -> fp16 scaled; K -> fp16 hi/lo; V -> fp16
    const int nb = n0 + wn * 64;
    const int region = nb >> 10;
    const int h = (nb & 1023) >> 6;
    __half* dh = region == 0 ? g_qh : region == 1 ? g_kh : g_vh;
    const bool has_lo = (region == 1);
    const float scale = (region == 0) ? QSCALE : 1.0f;

#pragma unroll
    for (int mi = 0; mi < 4; mi++) {
#pragma unroll
        for (int rr = 0; rr < 2; rr++) {
            const int m = m0 + wm * 64 + mi * 16 + (lane >> 2) + rr * 8;
            const int b = m >> 11, t = m & 2047;
            const size_t roff = (((size_t)b * HEADS + h) * TSEQ + t) * HD;
#pragma unroll
            for (int nj = 0; nj < 8; nj++) {
                const int d = nj * 8 + 2 * (lane & 3);
                float2 bv = *(const float2*)(bias + nb + d);
                float v0 = (acc[mi][nj][rr*2+0] + bv.x) * scale;
                float v1 = (acc[mi][nj][rr*2+1] + bv.y) * scale;
                __half h0 = __float2half(v0), h1 = __float2half(v1);
                *(__half2*)(dh + roff + d) = __half2(h0, h1);
                if (has_lo) {
                    float r0 = v0 - __half2float(h0);
                    float r1 = v1 - __half2float(h1);
                    *(__half2*)(g_kl + roff + d) =
                        __half2(__float2half(r0), __float2half(r1));
                }
            }
        }
    }
}

// ---------------------------------------------------------------------------
// Kernel 2: flash attention, fp16 mma.sync.
// S = qh*(kh + kl)  (2 MMAs, K exact, Q fp16-rounded);  P*V single fp16 MMA.
// MMA issue interleaved over 4 accumulators.
// ---------------------------------------------------------------------------
#define ASTR_B   144                // 64 fp16 (128B) + 16B pad
#define QTILE_B  (128*ASTR_B)       // 18432
#define KTILE_B  (64*ASTR_B)        // 9216
#define ABUF0    QTILE_B            // 18432
#define ABUF_B   (3*KTILE_B)        // 27648 (kh, kl, vh)

__device__ __forceinline__ void kv_load(uint32_t sbase, int tid, size_t krow0,
                                        int kb, int buf)
{
#pragma unroll
    for (int i = 0; i < 6; i++) {
        const int arr = i >> 1;                // 0 kh, 1 kl, 2 vh
        int rem = ((i & 1) << 8) + tid;        // 0..511
        int row = rem >> 3, q = rem & 7;
        const __half* g = (arr == 0 ? g_kh : arr == 1 ? g_kl : g_vh) +
                          (krow0 + (size_t)kb * 64 + row) * HD + q * 8;
        CP_ASYNC(sbase + ABUF0 + buf * ABUF_B + arr * KTILE_B + row * ASTR_B + q * 16, g);
    }
}

__global__ __launch_bounds__(256, 1) void attn_mma(float* __restrict__ out)
{
    extern __shared__ char sma[];
    const uint32_t sbase = smem_to_u32(sma);
    const int tid = threadIdx.x, lane = tid & 31, wid = tid >> 5;
    const int qbi = gridDim.x - 1 - blockIdx.x;
    const int bh = blockIdx.y;
    const int kmax = 2 * qbi + 2;
    const size_t qrow0 = (size_t)bh * TSEQ + (size_t)qbi * 128;
    const size_t krow0 = (size_t)bh * TSEQ;

    // Q (fp16, pre-scaled) -> smem
#pragma unroll
    for (int i = 0; i < 4; i++) {
        int rem = (i << 8) + tid;               // 0..1023
        int row = rem >> 3, q = rem & 7;
        const __half* g = g_qh + (qrow0 + row) * HD + q * 8;
        CP_ASYNC(sbase + row * ASTR_B + q * 16, g);
    }
    CP_COMMIT();
    kv_load(sbase, tid, krow0, 0, 0);
    CP_COMMIT();
    CP_WAIT1();
    __syncthreads();

    uint32_t qfh[4][4];
#pragma unroll
    for (int ks = 0; ks < 4; ks++) {
        uint32_t a = sbase + (wid * 16 + (lane & 15)) * ASTR_B +
                     (ks * 16 + ((lane >> 4) << 3)) * 2;
        ldsm4(qfh[ks], a);
    }

    float o[8][4];
#pragma unroll
    for (int nj = 0; nj < 8; nj++)
#pragma unroll
        for (int c = 0; c < 4; c++) o[nj][c] = 0.f;
    float m1 = -1e30f, m2 = -1e30f, l1 = 0.f, l2 = 0.f;

    for (int kb = 0; kb < kmax; kb++) {
        const int buf = kb & 1;
        if (kb + 1 < kmax) {
            kv_load(sbase, tid, krow0, kb + 1, buf ^ 1);
            CP_COMMIT();
            CP_WAIT1();
        } else {
            CP_WAIT0();
        }
        __syncthreads();

        const bool active = (kb * 64 <= qbi * 128 + wid * 16 + 15);
        if (active) {
            // ---- S = qh * (kh + kl): 2 MMAs, 4-acc interleave ----
            float s[8][4];
#pragma unroll
            for (int nj = 0; nj < 8; nj++)
#pragma unroll
                for (int c = 0; c < 4; c++) s[nj][c] = 0.f;

            const uint32_t kbase = sbase + ABUF0 + buf * ABUF_B;
#pragma unroll
            for (int ks = 0; ks < 4; ks++) {
                const uint32_t coff = (ks * 16 + ((lane >> 4) << 3)) * 2;
#pragma unroll
                for (int gp = 0; gp < 2; gp++) {
                    uint32_t ka[4], la[4], kb4[4], lb4[4];
                    uint32_t ra = kbase + (gp * 32 + (lane & 15)) * ASTR_B + coff;
                    uint32_t rb = ra + 16 * ASTR_B;
                    ldsm4(ka,  ra);
                    ldsm4(la,  ra + KTILE_B);
                    ldsm4(kb4, rb);
                    ldsm4(lb4, rb + KTILE_B);
                    mma_f16(s[4*gp+0], qfh[ks], ka[0],  ka[2]);
                    mma_f16(s[4*gp+1], qfh[ks], ka[1],  ka[3]);
                    mma_f16(s[4*gp+2], qfh[ks], kb4[0], kb4[2]);
                    mma_f16(s[4*gp+3], qfh[ks], kb4[1], kb4[3]);
                    mma_f16(s[4*gp+0], qfh[ks], la[0],  la[2]);
                    mma_f16(s[4*gp+1], qfh[ks], la[1],  la[3]);
                    mma_f16(s[4*gp+2], qfh[ks], lb4[0], lb4[2]);
                    mma_f16(s[4*gp+3], qfh[ks], lb4[1], lb4[3]);
                }
            }

            // ---- causal mask (diagonal band) ----
            if (kb >= 2 * qbi) {
                const int q1 = qbi * 128 + wid * 16 + (lane >> 2);
                const int tb = kb * 64 + 2 * (lane & 3);
#pragma unroll
                for (int nj = 0; nj < 8; nj++) {
                    const int t0 = tb + 8 * nj;
                    if (t0     > q1)     s[nj][0] = -1e30f;
                    if (t0 + 1 > q1)     s[nj][1] = -1e30f;
                    if (t0     > q1 + 8) s[nj][2] = -1e30f;
                    if (t0 + 1 > q1 + 8) s[nj][3] = -1e30f;
                }
            }

            // ---- online softmax, base-2 ----
            float mx1 = -1e30f, mx2 = -1e30f;
#pragma unroll
            for (int nj = 0; nj < 8; nj++) {
                mx1 = fmaxf(mx1, fmaxf(s[nj][0], s[nj][1]));
                mx2 = fmaxf(mx2, fmaxf(s[nj][2], s[nj][3]));
            }
            mx1 = fmaxf(mx1, __shfl_xor_sync(0xffffffffu, mx1, 1));
            mx1 = fmaxf(mx1, __shfl_xor_sync(0xffffffffu, mx1, 2));
            mx2 = fmaxf(mx2, __shfl_xor_sync(0xffffffffu, mx2, 1));
            mx2 = fmaxf(mx2, __shfl_xor_sync(0xffffffffu, mx2, 2));
            const float mn1 = fmaxf(m1, mx1), mn2 = fmaxf(m2, mx2);
            const float a1 = exp2f(m1 - mn1), a2 = exp2f(m2 - mn2);
            float rs1 = 0.f, rs2 = 0.f;
#pragma unroll
            for (int nj = 0; nj < 8; nj++) {
                s[nj][0] = exp2f(s[nj][0] - mn1);
                s[nj][1] = exp2f(s[nj][1] - mn1);
                s[nj][2] = exp2f(s[nj][2] - mn2);
                s[nj][3] = exp2f(s[nj][3] - mn2);
                rs1 += s[nj][0] + s[nj][1];
                rs2 += s[nj][2] + s[nj][3];
            }
            rs1 += __shfl_xor_sync(0xffffffffu, rs1, 1);
            rs1 += __shfl_xor_sync(0xffffffffu, rs1, 2);
            rs2 += __shfl_xor_sync(0xffffffffu, rs2, 1);
            rs2 += __shfl_xor_sync(0xffffffffu, rs2, 2);
            l1 = l1 * a1 + rs1;  l2 = l2 * a2 + rs2;
            m1 = mn1;            m2 = mn2;
#pragma unroll
            for (int nj = 0; nj < 8; nj++) {
                o[nj][0] *= a1; o[nj][1] *= a1;
                o[nj][2] *= a2; o[nj][3] *= a2;
            }

            // ---- O += P V (single fp16 MMA, 8-acc interleave) ----
            const uint32_t vbase = kbase + 2 * KTILE_B;
#pragma unroll
            for (int kt = 0; kt < 4; kt++) {
                uint32_t ph[4];
                {
                    const float* p0 = s[2 * kt];
                    const float* p1 = s[2 * kt + 1];
                    ph[0] = pack2h(__float2half(p0[0]), __float2half(p0[1]));
                    ph[1] = pack2h(__float2half(p0[2]), __float2half(p0[3]));
                    ph[2] = pack2h(__float2half(p1[0]), __float2half(p1[1]));
                    ph[3] = pack2h(__float2half(p1[2]), __float2half(p1[3]));
                }
#pragma unroll
                for (int g2 = 0; g2 < 4; g2++) {
                    uint32_t vh4[4];
                    uint32_t rb = vbase + (kt * 16 + (lane & 15)) * ASTR_B +
                                  (g2 * 16 + ((lane >> 4) << 3)) * 2;
                    ldsm4t(vh4, rb);
                    mma_f16(o[2*g2],   ph, vh4[0], vh4[1]);
                    mma_f16(o[2*g2+1], ph, vh4[2], vh4[3]);
                }
            }
        }
        __syncthreads();
    }

    // epilogue
    const float inv1 = 1.f / l1, inv2 = 1.f / l2;
    const int b = bh >> 4, h = bh & 15;
    const int t1 = qbi * 128 + wid * 16 + (lane >> 2);
    float* o1p = out + ((size_t)b * TSEQ + t1) * CDIM + h * 64 + 2 * (lane & 3);
    float* o2p = o1p + (size_t)8 * CDIM;
#pragma unroll
    for (int nj = 0; nj < 8; nj++) {
        *(float2*)(o1p + 8 * nj) = make_float2(o[nj][0] * inv1, o[nj][1] * inv1);
        *(float2*)(o2p + 8 * nj) = make_float2(o[nj][2] * inv2, o[nj][3] * inv2);
    }
}

// ---------------------------------------------------------------------------
extern "C" void kernel_launch(void* const* d_in, const int* in_sizes, int n_in,
                              void* d_out, int out_size)
{
    (void)in_sizes; (void)n_in; (void)out_size;
    const float* x  = (const float*)d_in[0];
    const float* w  = (const float*)d_in[1];
    const float* bb = (const float*)d_in[2];
    float* out = (float*)d_out;

    __nv_bfloat16 *xh, *xl, *wh, *wl;
    cudaGetSymbolAddress((void**)&xh, g_xh);
    cudaGetSymbolAddress((void**)&xl, g_xl);
    cudaGetSymbolAddress((void**)&wh, g_wh);
    cudaGetSymbolAddress((void**)&wl, g_wl);

    const int nx4 = BT * CDIM / 4;
    const int nw4 = NQKV * CDIM / 4;
    split_bf16<<<(nx4 + 255) / 256, 256>>>(x, xh, xl, nx4);
    split_bf16<<<(nw4 + 255) / 256, 256>>>(w, wh, wl, nw4);

    const int gsmem = 2 * GSTAGE_B;                     // 81920
    cudaFuncSetAttribute((const void*)qkv_gemm_mma,
                         cudaFuncAttributeMaxDynamicSharedMemorySize, gsmem);
    dim3 gg(NQKV / 128, BT / 128);                      // (24, 64)
    qkv_gemm_mma<<<gg, 128, gsmem>>>(bb);

    const int asmem = ABUF0 + 2 * ABUF_B;               // 73728
    cudaFuncSetAttribute((const void*)attn_mma,
                         cudaFuncAttributeMaxDynamicSharedMemorySize, asmem);
    dim3 ga(TSEQ / 128, NB * HEADS);                    // (16, 64)
    attn_mma<<<ga, 256, asmem>>>(out);
}

// round 6
// speedup vs baseline: 4.0353x; 1.1234x over previous
#include <cuda_runtime.h>
#include <cuda_fp16.h>
#include <cstdint>

#define NB    4
#define TSEQ  2048
#define CDIM  1024
#define HEADS 16
#define HD    64
#define BT    (NB*TSEQ)          // 8192
#define NQKV  3072

// Q pre-scale: 1/sqrt(64) * log2(e)  (softmax in base-2 domain)
#define QSCALE (0.125f * 1.44269504088896f)

// ---------------------------------------------------------------------------
// __device__ global scratch
// ---------------------------------------------------------------------------
__device__ __half g_xh[(size_t)BT*CDIM];
__device__ __half g_xl[(size_t)BT*CDIM];
__device__ __half g_wh[(size_t)NQKV*CDIM];
__device__ __half g_wl[(size_t)NQKV*CDIM];
// Q fp16 (scaled), K hi/lo fp16, V fp16 — all [B,H,T,D]
__device__ __half g_qh[(size_t)NB*HEADS*TSEQ*HD];
__device__ __half g_kh[(size_t)NB*HEADS*TSEQ*HD];
__device__ __half g_kl[(size_t)NB*HEADS*TSEQ*HD];
__device__ __half g_vh[(size_t)NB*HEADS*TSEQ*HD];

// ---------------------------------------------------------------------------
// Helpers
// ---------------------------------------------------------------------------
__device__ __forceinline__ uint32_t smem_to_u32(const void* p) {
    uint32_t a;
    asm("{ .reg .u64 t; cvta.to.shared.u64 t, %1; cvt.u32.u64 %0, t; }" : "=r"(a) : "l"(p));
    return a;
}
#define CP_ASYNC(dst, src) \
    asm volatile("cp.async.cg.shared.global [%0], [%1], 16;\n" :: "r"(dst), "l"(src))
#define CP_COMMIT() asm volatile("cp.async.commit_group;\n" ::: "memory")
#define CP_WAIT1()  asm volatile("cp.async.wait_group 1;\n" ::: "memory")
#define CP_WAIT0()  asm volatile("cp.async.wait_group 0;\n" ::: "memory")

__device__ __forceinline__ void ldsm4(uint32_t r[4], uint32_t a) {
    asm volatile("ldmatrix.sync.aligned.m8n8.x4.shared.b16 {%0,%1,%2,%3}, [%4];"
                 : "=r"(r[0]), "=r"(r[1]), "=r"(r[2]), "=r"(r[3]) : "r"(a));
}
__device__ __forceinline__ void ldsm4t(uint32_t r[4], uint32_t a) {
    asm volatile("ldmatrix.sync.aligned.m8n8.x4.trans.shared.b16 {%0,%1,%2,%3}, [%4];"
                 : "=r"(r[0]), "=r"(r[1]), "=r"(r[2]), "=r"(r[3]) : "r"(a));
}
__device__ __forceinline__ void mma_f16(float c[4], const uint32_t a[4],
                                        uint32_t b0, uint32_t b1) {
    asm volatile("mma.sync.aligned.m16n8k16.row.col.f32.f16.f16.f32 "
                 "{%0,%1,%2,%3}, {%4,%5,%6,%7}, {%8,%9}, {%0,%1,%2,%3};"
                 : "+f"(c[0]), "+f"(c[1]), "+f"(c[2]), "+f"(c[3])
                 : "r"(a[0]), "r"(a[1]), "r"(a[2]), "r"(a[3]), "r"(b0), "r"(b1));
}
__device__ __forceinline__ uint32_t pack2h(__half a, __half b) {
    __half2 t(a, b);
    return *reinterpret_cast<uint32_t*>(&t);
}

// ---------------------------------------------------------------------------
// Kernel 0: split fp32 -> fp16 hi/lo
// ---------------------------------------------------------------------------
__global__ __launch_bounds__(256) void split_fp16(const float* __restrict__ src,
                                                  __half* __restrict__ hi,
                                                  __half* __restrict__ lo,
                                                  int n4)
{
    int i = blockIdx.x * 256 + threadIdx.x;
    if (i >= n4) return;
    float4 v = ((const float4*)src)[i];
    __half h0 = __float2half(v.x), h1 = __float2half(v.y);
    __half h2 = __float2half(v.z), h3 = __float2half(v.w);
    __half l0 = __float2half(v.x - __half2float(h0));
    __half l1 = __float2half(v.y - __half2float(h1));
    __half l2 = __float2half(v.z - __half2float(h2));
    __half l3 = __float2half(v.w - __half2float(h3));
    __half2* hp = (__half2*)hi;
    __half2* lp = (__half2*)lo;
    hp[2*i]   = __half2(h0, h1);
    hp[2*i+1] = __half2(h2, h3);
    lp[2*i]   = __half2(l0, l1);
    lp[2*i+1] = __half2(l2, l3);
}

// ---------------------------------------------------------------------------
// Kernel 1: QKV GEMM, fp16 split mma.sync, term-major.
// Q/K regions: 2 terms (xh*wh + xh*wl), err ~2.8e-4. V region: 3 terms (exact
// to 2^-21). CTA 128x128, 4 warps (64x64), KC=32 double-buffered.
// ---------------------------------------------------------------------------
#define KCG      32
#define GSTR_B   80
#define GTILE_B  (128*GSTR_B)       // 10240
#define GSTAGE_B (4*GTILE_B)        // 40960

__device__ __forceinline__ void gemm_load(uint32_t sdst, int tid, int k0, int m0, int n0)
{
#pragma unroll
    for (int i = 0; i < 16; i++) {
        const int tile = i >> 2;                 // 0 xh, 1 xl, 2 wh, 3 wl
        int idx = ((i & 3) << 7) + tid;          // 0..511
        int row = idx >> 2, q = idx & 3;
        const __half* g =
            (tile == 0) ? g_xh + (size_t)(m0 + row) * CDIM :
            (tile == 1) ? g_xl + (size_t)(m0 + row) * CDIM :
            (tile == 2) ? g_wh + (size_t)(n0 + row) * CDIM :
                          g_wl + (size_t)(n0 + row) * CDIM;
        CP_ASYNC(sdst + tile * GTILE_B + row * GSTR_B + q * 16, g + k0 + q * 8);
    }
}

__global__ __launch_bounds__(128, 2) void qkv_gemm_mma(const float* __restrict__ bias)
{
    extern __shared__ char smg[];
    const uint32_t sbase = smem_to_u32(smg);
    const int tid = threadIdx.x, lane = tid & 31, wid = tid >> 5;
    const int m0 = blockIdx.y * 128, n0 = blockIdx.x * 128;
    const int wm = wid & 1, wn = wid >> 1;

    const int region = (n0 + wn * 64) >> 10;     // 0:Q 1:K 2:V (warp-uniform)
    const bool full3 = (region == 2);

    float acc[4][8][4];
#pragma unroll
    for (int mi = 0; mi < 4; mi++)
#pragma unroll
        for (int nj = 0; nj < 8; nj++)
#pragma unroll
            for (int c = 0; c < 4; c++) acc[mi][nj][c] = 0.f;

    gemm_load(sbase, tid, 0, m0, n0);
    CP_COMMIT();

    const int NCH = CDIM / KCG;     // 32
    for (int c = 0; c < NCH; c++) {
        const int buf = c & 1;
        if (c + 1 < NCH) {
            gemm_load(sbase + (buf ^ 1) * GSTAGE_B, tid, (c + 1) * KCG, m0, n0);
            CP_COMMIT();
            CP_WAIT1();
        } else {
            CP_WAIT0();
        }
        __syncthreads();

        const uint32_t bb = sbase + buf * GSTAGE_B;
#pragma unroll
        for (int ks = 0; ks < 2; ks++) {
            const uint32_t coff = (ks * 16 + ((lane >> 4) << 3)) * 2;
            uint32_t ah[4][4], al[4][4];
#pragma unroll
            for (int mi = 0; mi < 4; mi++) {
                uint32_t ra = bb + (wm * 64 + mi * 16 + (lane & 15)) * GSTR_B + coff;
                ldsm4(ah[mi], ra);
                if (full3) ldsm4(al[mi], ra + GTILE_B);
            }
#pragma unroll
            for (int g2 = 0; g2 < 4; g2++) {
                uint32_t bh4[4], bl4[4];
                uint32_t rb = bb + 2 * GTILE_B +
                              (wn * 64 + g2 * 16 + (lane & 15)) * GSTR_B + coff;
                ldsm4(bh4, rb);
                ldsm4(bl4, rb + GTILE_B);
                // term-major: 8 distinct accumulators between reuses
#pragma unroll
                for (int mi = 0; mi < 4; mi++) {
                    mma_f16(acc[mi][2*g2],   ah[mi], bh4[0], bh4[2]);
                    mma_f16(acc[mi][2*g2+1], ah[mi], bh4[1], bh4[3]);
                }
#pragma unroll
                for (int mi = 0; mi < 4; mi++) {
                    mma_f16(acc[mi][2*g2],   ah[mi], bl4[0], bl4[2]);
                    mma_f16(acc[mi][2*g2+1], ah[mi], bl4[1], bl4[3]);
                }
                if (full3) {
#pragma unroll
                    for (int mi = 0; mi < 4; mi++) {
                        mma_f16(acc[mi][2*g2],   al[mi], bh4[0], bh4[2]);
                        mma_f16(acc[mi][2*g2+1], al[mi], bh4[1], bh4[3]);
                    }
                }
            }
        }
        __syncthreads();
    }

    // epilogue: +bias; Q -> fp16 scaled; K -> fp16 hi/lo; V -> fp16
    const int nb = n0 + wn * 64;
    const int h = (nb & 1023) >> 6;
    __half* dh = region == 0 ? g_qh : region == 1 ? g_kh : g_vh;
    const bool has_lo = (region == 1);
    const float scale = (region == 0) ? QSCALE : 1.0f;

#pragma unroll
    for (int mi = 0; mi < 4; mi++) {
#pragma unroll
        for (int rr = 0; rr < 2; rr++) {
            const int m = m0 + wm * 64 + mi * 16 + (lane >> 2) + rr * 8;
            const int b = m >> 11, t = m & 2047;
            const size_t roff = (((size_t)b * HEADS + h) * TSEQ + t) * HD;
#pragma unroll
            for (int nj = 0; nj < 8; nj++) {
                const int d = nj * 8 + 2 * (lane & 3);
                float2 bv = *(const float2*)(bias + nb + d);
                float v0 = (acc[mi][nj][rr*2+0] + bv.x) * scale;
                float v1 = (acc[mi][nj][rr*2+1] + bv.y) * scale;
                __half h0 = __float2half(v0), h1 = __float2half(v1);
                *(__half2*)(dh + roff + d) = __half2(h0, h1);
                if (has_lo) {
                    float r0 = v0 - __half2float(h0);
                    float r1 = v1 - __half2float(h1);
                    *(__half2*)(g_kl + roff + d) =
                        __half2(__float2half(r0), __float2half(r1));
                }
            }
        }
    }
}

// ---------------------------------------------------------------------------
// Kernel 2: flash attention, fp16 mma.sync, 2 CTAs/SM (regs capped at 128).
// S = qh*(kh + kl); P*V single fp16 MMA. 4-acc interleave.
// ---------------------------------------------------------------------------
#define ASTR_B   144                // 64 fp16 (128B) + 16B pad
#define QTILE_B  (128*ASTR_B)       // 18432
#define KTILE_B  (64*ASTR_B)        // 9216
#define ABUF0    QTILE_B            // 18432
#define ABUF_B   (3*KTILE_B)        // 27648 (kh, kl, vh)

__device__ __forceinline__ void kv_load(uint32_t sbase, int tid, size_t krow0,
                                        int kb, int buf)
{
#pragma unroll
    for (int i = 0; i < 6; i++) {
        const int arr = i >> 1;                // 0 kh, 1 kl, 2 vh
        int rem = ((i & 1) << 8) + tid;        // 0..511
        int row = rem >> 3, q = rem & 7;
        const __half* g = (arr == 0 ? g_kh : arr == 1 ? g_kl : g_vh) +
                          (krow0 + (size_t)kb * 64 + row) * HD + q * 8;
        CP_ASYNC(sbase + ABUF0 + buf * ABUF_B + arr * KTILE_B + row * ASTR_B + q * 16, g);
    }
}

__global__ __launch_bounds__(256, 2) void attn_mma(float* __restrict__ out)
{
    extern __shared__ char sma[];
    const uint32_t sbase = smem_to_u32(sma);
    const int tid = threadIdx.x, lane = tid & 31, wid = tid >> 5;
    const int qbi = gridDim.x - 1 - blockIdx.x;
    const int bh = blockIdx.y;
    const int kmax = 2 * qbi + 2;
    const size_t qrow0 = (size_t)bh * TSEQ + (size_t)qbi * 128;
    const size_t krow0 = (size_t)bh * TSEQ;

    // Q (fp16, pre-scaled) -> smem
#pragma unroll
    for (int i = 0; i < 4; i++) {
        int rem = (i << 8) + tid;               // 0..1023
        int row = rem >> 3, q = rem & 7;
        const __half* g = g_qh + (qrow0 + row) * HD + q * 8;
        CP_ASYNC(sbase + row * ASTR_B + q * 16, g);
    }
    CP_COMMIT();
    kv_load(sbase, tid, krow0, 0, 0);
    CP_COMMIT();
    CP_WAIT1();
    __syncthreads();

    uint32_t qfh[4][4];
#pragma unroll
    for (int ks = 0; ks < 4; ks++) {
        uint32_t a = sbase + (wid * 16 + (lane & 15)) * ASTR_B +
                     (ks * 16 + ((lane >> 4) << 3)) * 2;
        ldsm4(qfh[ks], a);
    }

    float o[8][4];
#pragma unroll
    for (int nj = 0; nj < 8; nj++)
#pragma unroll
        for (int c = 0; c < 4; c++) o[nj][c] = 0.f;
    float m1 = -1e30f, m2 = -1e30f, l1 = 0.f, l2 = 0.f;

    for (int kb = 0; kb < kmax; kb++) {
        const int buf = kb & 1;
        if (kb + 1 < kmax) {
            kv_load(sbase, tid, krow0, kb + 1, buf ^ 1);
            CP_COMMIT();
            CP_WAIT1();
        } else {
            CP_WAIT0();
        }
        __syncthreads();

        const bool active = (kb * 64 <= qbi * 128 + wid * 16 + 15);
        if (active) {
            // ---- S = qh * (kh + kl): 2 MMAs per op, 4-acc interleave ----
            float s[8][4];
#pragma unroll
            for (int nj = 0; nj < 8; nj++)
#pragma unroll
                for (int c = 0; c < 4; c++) s[nj][c] = 0.f;

            const uint32_t kbase = sbase + ABUF0 + buf * ABUF_B;
#pragma unroll
            for (int ks = 0; ks < 4; ks++) {
                const uint32_t coff = (ks * 16 + ((lane >> 4) << 3)) * 2;
#pragma unroll
                for (int gp = 0; gp < 2; gp++) {
                    uint32_t ka[4], la[4], kb4[4], lb4[4];
                    uint32_t ra = kbase + (gp * 32 + (lane & 15)) * ASTR_B + coff;
                    uint32_t rb = ra + 16 * ASTR_B;
                    ldsm4(ka,  ra);
                    ldsm4(la,  ra + KTILE_B);
                    ldsm4(kb4, rb);
                    ldsm4(lb4, rb + KTILE_B);
                    mma_f16(s[4*gp+0], qfh[ks], ka[0],  ka[2]);
                    mma_f16(s[4*gp+1], qfh[ks], ka[1],  ka[3]);
                    mma_f16(s[4*gp+2], qfh[ks], kb4[0], kb4[2]);
                    mma_f16(s[4*gp+3], qfh[ks], kb4[1], kb4[3]);
                    mma_f16(s[4*gp+0], qfh[ks], la[0],  la[2]);
                    mma_f16(s[4*gp+1], qfh[ks], la[1],  la[3]);
                    mma_f16(s[4*gp+2], qfh[ks], lb4[0], lb4[2]);
                    mma_f16(s[4*gp+3], qfh[ks], lb4[1], lb4[3]);
                }
            }

            // ---- causal mask (diagonal band) ----
            if (kb >= 2 * qbi) {
                const int q1 = qbi * 128 + wid * 16 + (lane >> 2);
                const int tb = kb * 64 + 2 * (lane & 3);
#pragma unroll
                for (int nj = 0; nj < 8; nj++) {
                    const int t0 = tb + 8 * nj;
                    if (t0     > q1)     s[nj][0] = -1e30f;
                    if (t0 + 1 > q1)     s[nj][1] = -1e30f;
                    if (t0     > q1 + 8) s[nj][2] = -1e30f;
                    if (t0 + 1 > q1 + 8) s[nj][3] = -1e30f;
                }
            }

            // ---- online softmax, base-2 ----
            float mx1 = -1e30f, mx2 = -1e30f;
#pragma unroll
            for (int nj = 0; nj < 8; nj++) {
                mx1 = fmaxf(mx1, fmaxf(s[nj][0], s[nj][1]));
                mx2 = fmaxf(mx2, fmaxf(s[nj][2], s[nj][3]));
            }
            mx1 = fmaxf(mx1, __shfl_xor_sync(0xffffffffu, mx1, 1));
            mx1 = fmaxf(mx1, __shfl_xor_sync(0xffffffffu, mx1, 2));
            mx2 = fmaxf(mx2, __shfl_xor_sync(0xffffffffu, mx2, 1));
            mx2 = fmaxf(mx2, __shfl_xor_sync(0xffffffffu, mx2, 2));
            const float mn1 = fmaxf(m1, mx1), mn2 = fmaxf(m2, mx2);
            const float a1 = exp2f(m1 - mn1), a2 = exp2f(m2 - mn2);
            float rs1 = 0.f, rs2 = 0.f;
#pragma unroll
            for (int nj = 0; nj < 8; nj++) {
                s[nj][0] = exp2f(s[nj][0] - mn1);
                s[nj][1] = exp2f(s[nj][1] - mn1);
                s[nj][2] = exp2f(s[nj][2] - mn2);
                s[nj][3] = exp2f(s[nj][3] - mn2);
                rs1 += s[nj][0] + s[nj][1];
                rs2 += s[nj][2] + s[nj][3];
            }
            rs1 += __shfl_xor_sync(0xffffffffu, rs1, 1);
            rs1 += __shfl_xor_sync(0xffffffffu, rs1, 2);
            rs2 += __shfl_xor_sync(0xffffffffu, rs2, 1);
            rs2 += __shfl_xor_sync(0xffffffffu, rs2, 2);
            l1 = l1 * a1 + rs1;  l2 = l2 * a2 + rs2;
            m1 = mn1;            m2 = mn2;
#pragma unroll
            for (int nj = 0; nj < 8; nj++) {
                o[nj][0] *= a1; o[nj][1] *= a1;
                o[nj][2] *= a2; o[nj][3] *= a2;
            }

            // ---- O += P V (single fp16 MMA, 8-acc interleave) ----
            const uint32_t vbase = kbase + 2 * KTILE_B;
#pragma unroll
            for (int kt = 0; kt < 4; kt++) {
                uint32_t ph[4];
                {
                    const float* p0 = s[2 * kt];
                    const float* p1 = s[2 * kt + 1];
                    ph[0] = pack2h(__float2half(p0[0]), __float2half(p0[1]));
                    ph[1] = pack2h(__float2half(p0[2]), __float2half(p0[3]));
                    ph[2] = pack2h(__float2half(p1[0]), __float2half(p1[1]));
                    ph[3] = pack2h(__float2half(p1[2]), __float2half(p1[3]));
                }
#pragma unroll
                for (int g2 = 0; g2 < 4; g2++) {
                    uint32_t vh4[4];
                    uint32_t rb = vbase + (kt * 16 + (lane & 15)) * ASTR_B +
                                  (g2 * 16 + ((lane >> 4) << 3)) * 2;
                    ldsm4t(vh4, rb);
                    mma_f16(o[2*g2],   ph, vh4[0], vh4[1]);
                    mma_f16(o[2*g2+1], ph, vh4[2], vh4[3]);
                }
            }
        }
        __syncthreads();
    }

    // epilogue
    const float inv1 = 1.f / l1, inv2 = 1.f / l2;
    const int b = bh >> 4, h = bh & 15;
    const int t1 = qbi * 128 + wid * 16 + (lane >> 2);
    float* o1p = out + ((size_t)b * TSEQ + t1) * CDIM + h * 64 + 2 * (lane & 3);
    float* o2p = o1p + (size_t)8 * CDIM;
#pragma unroll
    for (int nj = 0; nj < 8; nj++) {
        *(float2*)(o1p + 8 * nj) = make_float2(o[nj][0] * inv1, o[nj][1] * inv1);
        *(float2*)(o2p + 8 * nj) = make_float2(o[nj][2] * inv2, o[nj][3] * inv2);
    }
}

// ---------------------------------------------------------------------------
extern "C" void kernel_launch(void* const* d_in, const int* in_sizes, int n_in,
                              void* d_out, int out_size)
{
    (void)in_sizes; (void)n_in; (void)out_size;
    const float* x  = (const float*)d_in[0];
    const float* w  = (const float*)d_in[1];
    const float* bb = (const float*)d_in[2];
    float* out = (float*)d_out;

    __half *xh, *xl, *wh, *wl;
    cudaGetSymbolAddress((void**)&xh, g_xh);
    cudaGetSymbolAddress((void**)&xl, g_xl);
    cudaGetSymbolAddress((void**)&wh, g_wh);
    cudaGetSymbolAddress((void**)&wl, g_wl);

    const int nx4 = BT * CDIM / 4;
    const int nw4 = NQKV * CDIM / 4;
    split_fp16<<<(nx4 + 255) / 256, 256>>>(x, xh, xl, nx4);
    split_fp16<<<(nw4 + 255) / 256, 256>>>(w, wh, wl, nw4);

    const int gsmem = 2 * GSTAGE_B;                     // 81920
    cudaFuncSetAttribute((const void*)qkv_gemm_mma,
                         cudaFuncAttributeMaxDynamicSharedMemorySize, gsmem);
    dim3 gg(NQKV / 128, BT / 128);                      // (24, 64)
    qkv_gemm_mma<<<gg, 128, gsmem>>>(bb);

    const int asmem = ABUF0 + 2 * ABUF_B;               // 73728
    cudaFuncSetAttribute((const void*)attn_mma,
                         cudaFuncAttributeMaxDynamicSharedMemorySize, asmem);
    dim3 ga(TSEQ / 128, NB * HEADS);                    // (16, 64)
    attn_mma<<<ga, 256, asmem>>>(out);
}

// round 7
// speedup vs baseline: 5.3427x; 1.3240x over previous
#include <cuda_runtime.h>
#include <cuda_fp16.h>
#include <cstdint>

#define NB    4
#define TSEQ  2048
#define CDIM  1024
#define HEADS 16
#define HD    64
#define BT    (NB*TSEQ)          // 8192
#define NQKV  3072

// Q pre-scale: 1/sqrt(64) * log2(e)  (softmax in base-2 domain)
#define QSCALE (0.125f * 1.44269504088896f)

// ---------------------------------------------------------------------------
// __device__ global scratch
// ---------------------------------------------------------------------------
__device__ __half g_xh[(size_t)BT*CDIM];
__device__ __half g_wh[(size_t)NQKV*CDIM];
__device__ __half g_wl[(size_t)NQKV*CDIM];
// Q fp16 (scaled), K fp16, V fp16 — all [B,H,T,D]
__device__ __half g_qh[(size_t)NB*HEADS*TSEQ*HD];
__device__ __half g_kh[(size_t)NB*HEADS*TSEQ*HD];
__device__ __half g_vh[(size_t)NB*HEADS*TSEQ*HD];

// ---------------------------------------------------------------------------
// Helpers
// ---------------------------------------------------------------------------
__device__ __forceinline__ uint32_t smem_to_u32(const void* p) {
    uint32_t a;
    asm("{ .reg .u64 t; cvta.to.shared.u64 t, %1; cvt.u32.u64 %0, t; }" : "=r"(a) : "l"(p));
    return a;
}
#define CP_ASYNC(dst, src) \
    asm volatile("cp.async.cg.shared.global [%0], [%1], 16;\n" :: "r"(dst), "l"(src))
#define CP_COMMIT() asm volatile("cp.async.commit_group;\n" ::: "memory")
#define CP_WAIT1()  asm volatile("cp.async.wait_group 1;\n" ::: "memory")
#define CP_WAIT0()  asm volatile("cp.async.wait_group 0;\n" ::: "memory")

__device__ __forceinline__ void ldsm4(uint32_t r[4], uint32_t a) {
    asm volatile("ldmatrix.sync.aligned.m8n8.x4.shared.b16 {%0,%1,%2,%3}, [%4];"
                 : "=r"(r[0]), "=r"(r[1]), "=r"(r[2]), "=r"(r[3]) : "r"(a));
}
__device__ __forceinline__ void ldsm4t(uint32_t r[4], uint32_t a) {
    asm volatile("ldmatrix.sync.aligned.m8n8.x4.trans.shared.b16 {%0,%1,%2,%3}, [%4];"
                 : "=r"(r[0]), "=r"(r[1]), "=r"(r[2]), "=r"(r[3]) : "r"(a));
}
__device__ __forceinline__ void mma_f16(float c[4], const uint32_t a[4],
                                        uint32_t b0, uint32_t b1) {
    asm volatile("mma.sync.aligned.m16n8k16.row.col.f32.f16.f16.f32 "
                 "{%0,%1,%2,%3}, {%4,%5,%6,%7}, {%8,%9}, {%0,%1,%2,%3};"
                 : "+f"(c[0]), "+f"(c[1]), "+f"(c[2]), "+f"(c[3])
                 : "r"(a[0]), "r"(a[1]), "r"(a[2]), "r"(a[3]), "r"(b0), "r"(b1));
}
__device__ __forceinline__ uint32_t pack2h(__half a, __half b) {
    __half2 t(a, b);
    return *reinterpret_cast<uint32_t*>(&t);
}

// ---------------------------------------------------------------------------
// Kernel 0a: fp32 -> fp16 convert (x)
// ---------------------------------------------------------------------------
__global__ __launch_bounds__(256) void conv_fp16(const float* __restrict__ src,
                                                 __half* __restrict__ dst, int n4)
{
    int i = blockIdx.x * 256 + threadIdx.x;
    if (i >= n4) return;
    float4 v = ((const float4*)src)[i];
    __half2* dp = (__half2*)dst;
    dp[2*i]   = __half2(__float2half(v.x), __float2half(v.y));
    dp[2*i+1] = __half2(__float2half(v.z), __float2half(v.w));
}

// ---------------------------------------------------------------------------
// Kernel 0b: fp32 -> fp16 hi/lo split (w)
// ---------------------------------------------------------------------------
__global__ __launch_bounds__(256) void split_fp16(const float* __restrict__ src,
                                                  __half* __restrict__ hi,
                                                  __half* __restrict__ lo,
                                                  int n4)
{
    int i = blockIdx.x * 256 + threadIdx.x;
    if (i >= n4) return;
    float4 v = ((const float4*)src)[i];
    __half h0 = __float2half(v.x), h1 = __float2half(v.y);
    __half h2 = __float2half(v.z), h3 = __float2half(v.w);
    __half l0 = __float2half(v.x - __half2float(h0));
    __half l1 = __float2half(v.y - __half2float(h1));
    __half l2 = __float2half(v.z - __half2float(h2));
    __half l3 = __float2half(v.w - __half2float(h3));
    __half2* hp = (__half2*)hi;
    __half2* lp = (__half2*)lo;
    hp[2*i]   = __half2(h0, h1);
    hp[2*i+1] = __half2(h2, h3);
    lp[2*i]   = __half2(l0, l1);
    lp[2*i+1] = __half2(l2, l3);
}

// ---------------------------------------------------------------------------
// Kernel 1: QKV GEMM = xh * (wh + wl), 2 fp16 MMA terms everywhere.
// CTA 128x128, 4 warps (64x64), KC=32 double-buffered, 3 smem tiles/stage.
// ---------------------------------------------------------------------------
#define KCG      32
#define GSTR_B   80
#define GTILE_B  (128*GSTR_B)       // 10240
#define GSTAGE_B (3*GTILE_B)        // 30720

__device__ __forceinline__ void gemm_load(uint32_t sdst, int tid, int k0, int m0, int n0)
{
#pragma unroll
    for (int i = 0; i < 12; i++) {
        const int tile = i >> 2;                 // 0 xh, 1 wh, 2 wl
        int idx = ((i & 3) << 7) + tid;          // 0..511
        int row = idx >> 2, q = idx & 3;
        const __half* g =
            (tile == 0) ? g_xh + (size_t)(m0 + row) * CDIM :
            (tile == 1) ? g_wh + (size_t)(n0 + row) * CDIM :
                          g_wl + (size_t)(n0 + row) * CDIM;
        CP_ASYNC(sdst + tile * GTILE_B + row * GSTR_B + q * 16, g + k0 + q * 8);
    }
}

__global__ __launch_bounds__(128, 2) void qkv_gemm_mma(const float* __restrict__ bias)
{
    extern __shared__ char smg[];
    const uint32_t sbase = smem_to_u32(smg);
    const int tid = threadIdx.x, lane = tid & 31, wid = tid >> 5;
    const int m0 = blockIdx.y * 128, n0 = blockIdx.x * 128;
    const int wm = wid & 1, wn = wid >> 1;

    float acc[4][8][4];
#pragma unroll
    for (int mi = 0; mi < 4; mi++)
#pragma unroll
        for (int nj = 0; nj < 8; nj++)
#pragma unroll
            for (int c = 0; c < 4; c++) acc[mi][nj][c] = 0.f;

    gemm_load(sbase, tid, 0, m0, n0);
    CP_COMMIT();

    const int NCH = CDIM / KCG;     // 32
    for (int c = 0; c < NCH; c++) {
        const int buf = c & 1;
        if (c + 1 < NCH) {
            gemm_load(sbase + (buf ^ 1) * GSTAGE_B, tid, (c + 1) * KCG, m0, n0);
            CP_COMMIT();
            CP_WAIT1();
        } else {
            CP_WAIT0();
        }
        __syncthreads();

        const uint32_t bb = sbase + buf * GSTAGE_B;
#pragma unroll
        for (int ks = 0; ks < 2; ks++) {
            const uint32_t coff = (ks * 16 + ((lane >> 4) << 3)) * 2;
            uint32_t ah[4][4];
#pragma unroll
            for (int mi = 0; mi < 4; mi++) {
                uint32_t ra = bb + (wm * 64 + mi * 16 + (lane & 15)) * GSTR_B + coff;
                ldsm4(ah[mi], ra);
            }
#pragma unroll
            for (int g2 = 0; g2 < 4; g2++) {
                uint32_t bh4[4], bl4[4];
                uint32_t rb = bb + GTILE_B +
                              (wn * 64 + g2 * 16 + (lane & 15)) * GSTR_B + coff;
                ldsm4(bh4, rb);
                ldsm4(bl4, rb + GTILE_B);
                // term-major: 8 distinct accumulators between reuses
#pragma unroll
                for (int mi = 0; mi < 4; mi++) {
                    mma_f16(acc[mi][2*g2],   ah[mi], bh4[0], bh4[2]);
                    mma_f16(acc[mi][2*g2+1], ah[mi], bh4[1], bh4[3]);
                }
#pragma unroll
                for (int mi = 0; mi < 4; mi++) {
                    mma_f16(acc[mi][2*g2],   ah[mi], bl4[0], bl4[2]);
                    mma_f16(acc[mi][2*g2+1], ah[mi], bl4[1], bl4[3]);
                }
            }
        }
        __syncthreads();
    }

    // epilogue: +bias; Q scaled; all regions -> fp16
    const int nb = n0 + wn * 64;
    const int region = nb >> 10;
    const int h = (nb & 1023) >> 6;
    __half* dh = region == 0 ? g_qh : region == 1 ? g_kh : g_vh;
    const float scale = (region == 0) ? QSCALE : 1.0f;

#pragma unroll
    for (int mi = 0; mi < 4; mi++) {
#pragma unroll
        for (int rr = 0; rr < 2; rr++) {
            const int m = m0 + wm * 64 + mi * 16 + (lane >> 2) + rr * 8;
            const int b = m >> 11, t = m & 2047;
            const size_t roff = (((size_t)b * HEADS + h) * TSEQ + t) * HD;
#pragma unroll
            for (int nj = 0; nj < 8; nj++) {
                const int d = nj * 8 + 2 * (lane & 3);
                float2 bv = *(const float2*)(bias + nb + d);
                float v0 = (acc[mi][nj][rr*2+0] + bv.x) * scale;
                float v1 = (acc[mi][nj][rr*2+1] + bv.y) * scale;
                *(__half2*)(dh + roff + d) =
                    __half2(__float2half(v0), __float2half(v1));
            }
        }
    }
}

// ---------------------------------------------------------------------------
// Kernel 2: flash attention, fp16 mma.sync, 2 CTAs/SM.
// S = qh*kh (1 MMA); P*V single fp16 MMA. 4-acc interleave.
// ---------------------------------------------------------------------------
#define ASTR_B   144                // 64 fp16 (128B) + 16B pad
#define QTILE_B  (128*ASTR_B)       // 18432
#define KTILE_B  (64*ASTR_B)        // 9216
#define ABUF0    QTILE_B            // 18432
#define ABUF_B   (2*KTILE_B)        // 18432 (kh, vh)

__device__ __forceinline__ void kv_load(uint32_t sbase, int tid, size_t krow0,
                                        int kb, int buf)
{
#pragma unroll
    for (int i = 0; i < 4; i++) {
        const int arr = i >> 1;                // 0 kh, 1 vh
        int rem = ((i & 1) << 8) + tid;        // 0..511
        int row = rem >> 3, q = rem & 7;
        const __half* g = (arr == 0 ? g_kh : g_vh) +
                          (krow0 + (size_t)kb * 64 + row) * HD + q * 8;
        CP_ASYNC(sbase + ABUF0 + buf * ABUF_B + arr * KTILE_B + row * ASTR_B + q * 16, g);
    }
}

__global__ __launch_bounds__(256, 2) void attn_mma(float* __restrict__ out)
{
    extern __shared__ char sma[];
    const uint32_t sbase = smem_to_u32(sma);
    const int tid = threadIdx.x, lane = tid & 31, wid = tid >> 5;
    const int qbi = gridDim.x - 1 - blockIdx.x;
    const int bh = blockIdx.y;
    const int kmax = 2 * qbi + 2;
    const size_t qrow0 = (size_t)bh * TSEQ + (size_t)qbi * 128;
    const size_t krow0 = (size_t)bh * TSEQ;

    // Q (fp16, pre-scaled) -> smem
#pragma unroll
    for (int i = 0; i < 4; i++) {
        int rem = (i << 8) + tid;               // 0..1023
        int row = rem >> 3, q = rem & 7;
        const __half* g = g_qh + (qrow0 + row) * HD + q * 8;
        CP_ASYNC(sbase + row * ASTR_B + q * 16, g);
    }
    CP_COMMIT();
    kv_load(sbase, tid, krow0, 0, 0);
    CP_COMMIT();
    CP_WAIT1();
    __syncthreads();

    uint32_t qfh[4][4];
#pragma unroll
    for (int ks = 0; ks < 4; ks++) {
        uint32_t a = sbase + (wid * 16 + (lane & 15)) * ASTR_B +
                     (ks * 16 + ((lane >> 4) << 3)) * 2;
        ldsm4(qfh[ks], a);
    }

    float o[8][4];
#pragma unroll
    for (int nj = 0; nj < 8; nj++)
#pragma unroll
        for (int c = 0; c < 4; c++) o[nj][c] = 0.f;
    float m1 = -1e30f, m2 = -1e30f, l1 = 0.f, l2 = 0.f;

    for (int kb = 0; kb < kmax; kb++) {
        const int buf = kb & 1;
        if (kb + 1 < kmax) {
            kv_load(sbase, tid, krow0, kb + 1, buf ^ 1);
            CP_COMMIT();
            CP_WAIT1();
        } else {
            CP_WAIT0();
        }
        __syncthreads();

        const bool active = (kb * 64 <= qbi * 128 + wid * 16 + 15);
        if (active) {
            // ---- S = qh * kh: 1 MMA per op, 4-acc interleave ----
            float s[8][4];
#pragma unroll
            for (int nj = 0; nj < 8; nj++)
#pragma unroll
                for (int c = 0; c < 4; c++) s[nj][c] = 0.f;

            const uint32_t kbase = sbase + ABUF0 + buf * ABUF_B;
#pragma unroll
            for (int ks = 0; ks < 4; ks++) {
                const uint32_t coff = (ks * 16 + ((lane >> 4) << 3)) * 2;
#pragma unroll
                for (int gp = 0; gp < 2; gp++) {
                    uint32_t ka[4], kb4[4];
                    uint32_t ra = kbase + (gp * 32 + (lane & 15)) * ASTR_B + coff;
                    uint32_t rb = ra + 16 * ASTR_B;
                    ldsm4(ka,  ra);
                    ldsm4(kb4, rb);
                    mma_f16(s[4*gp+0], qfh[ks], ka[0],  ka[2]);
                    mma_f16(s[4*gp+1], qfh[ks], ka[1],  ka[3]);
                    mma_f16(s[4*gp+2], qfh[ks], kb4[0], kb4[2]);
                    mma_f16(s[4*gp+3], qfh[ks], kb4[1], kb4[3]);
                }
            }

            // ---- causal mask (diagonal band) ----
            if (kb >= 2 * qbi) {
                const int q1 = qbi * 128 + wid * 16 + (lane >> 2);
                const int tb = kb * 64 + 2 * (lane & 3);
#pragma unroll
                for (int nj = 0; nj < 8; nj++) {
                    const int t0 = tb + 8 * nj;
                    if (t0     > q1)     s[nj][0] = -1e30f;
                    if (t0 + 1 > q1)     s[nj][1] = -1e30f;
                    if (t0     > q1 + 8) s[nj][2] = -1e30f;
                    if (t0 + 1 > q1 + 8) s[nj][3] = -1e30f;
                }
            }

            // ---- online softmax, base-2 ----
            float mx1 = -1e30f, mx2 = -1e30f;
#pragma unroll
            for (int nj = 0; nj < 8; nj++) {
                mx1 = fmaxf(mx1, fmaxf(s[nj][0], s[nj][1]));
                mx2 = fmaxf(mx2, fmaxf(s[nj][2], s[nj][3]));
            }
            mx1 = fmaxf(mx1, __shfl_xor_sync(0xffffffffu, mx1, 1));
            mx1 = fmaxf(mx1, __shfl_xor_sync(0xffffffffu, mx1, 2));
            mx2 = fmaxf(mx2, __shfl_xor_sync(0xffffffffu, mx2, 1));
            mx2 = fmaxf(mx2, __shfl_xor_sync(0xffffffffu, mx2, 2));
            const float mn1 = fmaxf(m1, mx1), mn2 = fmaxf(m2, mx2);
            const float a1 = exp2f(m1 - mn1), a2 = exp2f(m2 - mn2);
            float rs1 = 0.f, rs2 = 0.f;
#pragma unroll
            for (int nj = 0; nj < 8; nj++) {
                s[nj][0] = exp2f(s[nj][0] - mn1);
                s[nj][1] = exp2f(s[nj][1] - mn1);
                s[nj][2] = exp2f(s[nj][2] - mn2);
                s[nj][3] = exp2f(s[nj][3] - mn2);
                rs1 += s[nj][0] + s[nj][1];
                rs2 += s[nj][2] + s[nj][3];
            }
            rs1 += __shfl_xor_sync(0xffffffffu, rs1, 1);
            rs1 += __shfl_xor_sync(0xffffffffu, rs1, 2);
            rs2 += __shfl_xor_sync(0xffffffffu, rs2, 1);
            rs2 += __shfl_xor_sync(0xffffffffu, rs2, 2);
            l1 = l1 * a1 + rs1;  l2 = l2 * a2 + rs2;
            m1 = mn1;            m2 = mn2;
#pragma unroll
            for (int nj = 0; nj < 8; nj++) {
                o[nj][0] *= a1; o[nj][1] *= a1;
                o[nj][2] *= a2; o[nj][3] *= a2;
            }

            // ---- O += P V (single fp16 MMA, 8-acc interleave) ----
            const uint32_t vbase = kbase + KTILE_B;
#pragma unroll
            for (int kt = 0; kt < 4; kt++) {
                uint32_t ph[4];
                {
                    const float* p0 = s[2 * kt];
                    const float* p1 = s[2 * kt + 1];
                    ph[0] = pack2h(__float2half(p0[0]), __float2half(p0[1]));
                    ph[1] = pack2h(__float2half(p0[2]), __float2half(p0[3]));
                    ph[2] = pack2h(__float2half(p1[0]), __float2half(p1[1]));
                    ph[3] = pack2h(__float2half(p1[2]), __float2half(p1[3]));
                }
#pragma unroll
                for (int g2 = 0; g2 < 4; g2++) {
                    uint32_t vh4[4];
                    uint32_t rb = vbase + (kt * 16 + (lane & 15)) * ASTR_B +
                                  (g2 * 16 + ((lane >> 4) << 3)) * 2;
                    ldsm4t(vh4, rb);
                    mma_f16(o[2*g2],   ph, vh4[0], vh4[1]);
                    mma_f16(o[2*g2+1], ph, vh4[2], vh4[3]);
                }
            }
        }
        __syncthreads();
    }

    // epilogue
    const float inv1 = 1.f / l1, inv2 = 1.f / l2;
    const int b = bh >> 4, h = bh & 15;
    const int t1 = qbi * 128 + wid * 16 + (lane >> 2);
    float* o1p = out + ((size_t)b * TSEQ + t1) * CDIM + h * 64 + 2 * (lane & 3);
    float* o2p = o1p + (size_t)8 * CDIM;
#pragma unroll
    for (int nj = 0; nj < 8; nj++) {
        *(float2*)(o1p + 8 * nj) = make_float2(o[nj][0] * inv1, o[nj][1] * inv1);
        *(float2*)(o2p + 8 * nj) = make_float2(o[nj][2] * inv2, o[nj][3] * inv2);
    }
}

// ---------------------------------------------------------------------------
extern "C" void kernel_launch(void* const* d_in, const int* in_sizes, int n_in,
                              void* d_out, int out_size)
{
    (void)in_sizes; (void)n_in; (void)out_size;
    const float* x  = (const float*)d_in[0];
    const float* w  = (const float*)d_in[1];
    const float* bb = (const float*)d_in[2];
    float* out = (float*)d_out;

    __half *xh, *wh, *wl;
    cudaGetSymbolAddress((void**)&xh, g_xh);
    cudaGetSymbolAddress((void**)&wh, g_wh);
    cudaGetSymbolAddress((void**)&wl, g_wl);

    const int nx4 = BT * CDIM / 4;
    const int nw4 = NQKV * CDIM / 4;
    conv_fp16<<<(nx4 + 255) / 256, 256>>>(x, xh, nx4);
    split_fp16<<<(nw4 + 255) / 256, 256>>>(w, wh, wl, nw4);

    const int gsmem = 2 * GSTAGE_B;                     // 61440
    cudaFuncSetAttribute((const void*)qkv_gemm_mma,
                         cudaFuncAttributeMaxDynamicSharedMemorySize, gsmem);
    dim3 gg(NQKV / 128, BT / 128);                      // (24, 64)
    qkv_gemm_mma<<<gg, 128, gsmem>>>(bb);

    const int asmem = ABUF0 + 2 * ABUF_B;               // 55296
    cudaFuncSetAttribute((const void*)attn_mma,
                         cudaFuncAttributeMaxDynamicSharedMemorySize, asmem);
    dim3 ga(TSEQ / 128, NB * HEADS);                    // (16, 64)
    attn_mma<<<ga, 256, asmem>>>(out);
}

// round 8
// speedup vs baseline: 7.3087x; 1.3680x over previous
#include <cuda_runtime.h>
#include <cuda_fp16.h>
#include <cstdint>

#define NB    4
#define TSEQ  2048
#define CDIM  1024
#define HEADS 16
#define HD    64
#define BT    (NB*TSEQ)          // 8192
#define NQKV  3072

// Q pre-scale: 1/sqrt(64) * log2(e)  (softmax in base-2 domain)
#define QSCALE (0.125f * 1.44269504088896f)

// ---------------------------------------------------------------------------
// __device__ global scratch
// ---------------------------------------------------------------------------
__device__ __half g_xh[(size_t)BT*CDIM];
__device__ __half g_wh[(size_t)NQKV*CDIM];
// Q fp16 (scaled), K fp16, V fp16 — all [B,H,T,D]
__device__ __half g_qh[(size_t)NB*HEADS*TSEQ*HD];
__device__ __half g_kh[(size_t)NB*HEADS*TSEQ*HD];
__device__ __half g_vh[(size_t)NB*HEADS*TSEQ*HD];

// ---------------------------------------------------------------------------
// Helpers
// ---------------------------------------------------------------------------
__device__ __forceinline__ uint32_t smem_to_u32(const void* p) {
    uint32_t a;
    asm("{ .reg .u64 t; cvta.to.shared.u64 t, %1; cvt.u32.u64 %0, t; }" : "=r"(a) : "l"(p));
    return a;
}
#define CP_ASYNC(dst, src) \
    asm volatile("cp.async.cg.shared.global [%0], [%1], 16;\n" :: "r"(dst), "l"(src))
#define CP_COMMIT() asm volatile("cp.async.commit_group;\n" ::: "memory")
#define CP_WAIT1()  asm volatile("cp.async.wait_group 1;\n" ::: "memory")
#define CP_WAIT0()  asm volatile("cp.async.wait_group 0;\n" ::: "memory")

__device__ __forceinline__ void ldsm4(uint32_t r[4], uint32_t a) {
    asm volatile("ldmatrix.sync.aligned.m8n8.x4.shared.b16 {%0,%1,%2,%3}, [%4];"
                 : "=r"(r[0]), "=r"(r[1]), "=r"(r[2]), "=r"(r[3]) : "r"(a));
}
__device__ __forceinline__ void ldsm4t(uint32_t r[4], uint32_t a) {
    asm volatile("ldmatrix.sync.aligned.m8n8.x4.trans.shared.b16 {%0,%1,%2,%3}, [%4];"
                 : "=r"(r[0]), "=r"(r[1]), "=r"(r[2]), "=r"(r[3]) : "r"(a));
}
__device__ __forceinline__ void mma_f16(float c[4], const uint32_t a[4],
                                        uint32_t b0, uint32_t b1) {
    asm volatile("mma.sync.aligned.m16n8k16.row.col.f32.f16.f16.f32 "
                 "{%0,%1,%2,%3}, {%4,%5,%6,%7}, {%8,%9}, {%0,%1,%2,%3};"
                 : "+f"(c[0]), "+f"(c[1]), "+f"(c[2]), "+f"(c[3])
                 : "r"(a[0]), "r"(a[1]), "r"(a[2]), "r"(a[3]), "r"(b0), "r"(b1));
}
__device__ __forceinline__ uint32_t pack2h(__half a, __half b) {
    __half2 t(a, b);
    return *reinterpret_cast<uint32_t*>(&t);
}

// ---------------------------------------------------------------------------
// Kernel 0: fused fp32 -> fp16 convert for x and w (one launch)
// ---------------------------------------------------------------------------
__global__ __launch_bounds__(256) void conv_all(const float* __restrict__ x,
                                                const float* __restrict__ w,
                                                int nx4, int nw4)
{
    int i = blockIdx.x * 256 + threadIdx.x;
    const float* src;
    __half2* dp;
    int j;
    if (i < nx4) {
        src = x; dp = (__half2*)g_xh; j = i;
    } else {
        j = i - nx4;
        if (j >= nw4) return;
        src = w; dp = (__half2*)g_wh;
    }
    float4 v = ((const float4*)src)[j];
    dp[2*j]   = __half2(__float2half(v.x), __float2half(v.y));
    dp[2*j+1] = __half2(__float2half(v.z), __float2half(v.w));
}

// ---------------------------------------------------------------------------
// Kernel 1: QKV GEMM = xh * wh, single fp16 MMA per product.
// CTA 128x128, 4 warps (64x64), KC=32 double-buffered, 2 smem tiles/stage.
// ---------------------------------------------------------------------------
#define KCG      32
#define GSTR_B   80
#define GTILE_B  (128*GSTR_B)       // 10240
#define GSTAGE_B (2*GTILE_B)        // 20480

__device__ __forceinline__ void gemm_load(uint32_t sdst, int tid, int k0, int m0, int n0)
{
#pragma unroll
    for (int i = 0; i < 8; i++) {
        const int tile = i >> 2;                 // 0 xh, 1 wh
        int idx = ((i & 3) << 7) + tid;          // 0..511
        int row = idx >> 2, q = idx & 3;
        const __half* g =
            (tile == 0) ? g_xh + (size_t)(m0 + row) * CDIM :
                          g_wh + (size_t)(n0 + row) * CDIM;
        CP_ASYNC(sdst + tile * GTILE_B + row * GSTR_B + q * 16, g + k0 + q * 8);
    }
}

__global__ __launch_bounds__(128, 2) void qkv_gemm_mma(const float* __restrict__ bias)
{
    extern __shared__ char smg[];
    const uint32_t sbase = smem_to_u32(smg);
    const int tid = threadIdx.x, lane = tid & 31, wid = tid >> 5;
    const int m0 = blockIdx.y * 128, n0 = blockIdx.x * 128;
    const int wm = wid & 1, wn = wid >> 1;

    float acc[4][8][4];
#pragma unroll
    for (int mi = 0; mi < 4; mi++)
#pragma unroll
        for (int nj = 0; nj < 8; nj++)
#pragma unroll
            for (int c = 0; c < 4; c++) acc[mi][nj][c] = 0.f;

    gemm_load(sbase, tid, 0, m0, n0);
    CP_COMMIT();

    const int NCH = CDIM / KCG;     // 32
    for (int c = 0; c < NCH; c++) {
        const int buf = c & 1;
        if (c + 1 < NCH) {
            gemm_load(sbase + (buf ^ 1) * GSTAGE_B, tid, (c + 1) * KCG, m0, n0);
            CP_COMMIT();
            CP_WAIT1();
        } else {
            CP_WAIT0();
        }
        __syncthreads();

        const uint32_t bb = sbase + buf * GSTAGE_B;
#pragma unroll
        for (int ks = 0; ks < 2; ks++) {
            const uint32_t coff = (ks * 16 + ((lane >> 4) << 3)) * 2;
            uint32_t ah[4][4];
#pragma unroll
            for (int mi = 0; mi < 4; mi++) {
                uint32_t ra = bb + (wm * 64 + mi * 16 + (lane & 15)) * GSTR_B + coff;
                ldsm4(ah[mi], ra);
            }
#pragma unroll
            for (int g2 = 0; g2 < 4; g2++) {
                uint32_t bh4[4];
                uint32_t rb = bb + GTILE_B +
                              (wn * 64 + g2 * 16 + (lane & 15)) * GSTR_B + coff;
                ldsm4(bh4, rb);
#pragma unroll
                for (int mi = 0; mi < 4; mi++) {
                    mma_f16(acc[mi][2*g2],   ah[mi], bh4[0], bh4[2]);
                    mma_f16(acc[mi][2*g2+1], ah[mi], bh4[1], bh4[3]);
                }
            }
        }
        __syncthreads();
    }

    // epilogue: +bias; Q scaled; all regions -> fp16
    const int nb = n0 + wn * 64;
    const int region = nb >> 10;
    const int h = (nb & 1023) >> 6;
    __half* dh = region == 0 ? g_qh : region == 1 ? g_kh : g_vh;
    const float scale = (region == 0) ? QSCALE : 1.0f;

#pragma unroll
    for (int mi = 0; mi < 4; mi++) {
#pragma unroll
        for (int rr = 0; rr < 2; rr++) {
            const int m = m0 + wm * 64 + mi * 16 + (lane >> 2) + rr * 8;
            const int b = m >> 11, t = m & 2047;
            const size_t roff = (((size_t)b * HEADS + h) * TSEQ + t) * HD;
#pragma unroll
            for (int nj = 0; nj < 8; nj++) {
                const int d = nj * 8 + 2 * (lane & 3);
                float2 bv = *(const float2*)(bias + nb + d);
                float v0 = (acc[mi][nj][rr*2+0] + bv.x) * scale;
                float v1 = (acc[mi][nj][rr*2+1] + bv.y) * scale;
                *(__half2*)(dh + roff + d) =
                    __half2(__float2half(v0), __float2half(v1));
            }
        }
    }
}

// ---------------------------------------------------------------------------
// Kernel 2: flash attention, fp16 mma.sync, 2 CTAs/SM.
// S = qh*kh (1 MMA); P*V single fp16 MMA. 4-acc interleave.
// ---------------------------------------------------------------------------
#define ASTR_B   144                // 64 fp16 (128B) + 16B pad
#define QTILE_B  (128*ASTR_B)       // 18432
#define KTILE_B  (64*ASTR_B)        // 9216
#define ABUF0    QTILE_B            // 18432
#define ABUF_B   (2*KTILE_B)        // 18432 (kh, vh)

__device__ __forceinline__ void kv_load(uint32_t sbase, int tid, size_t krow0,
                                        int kb, int buf)
{
#pragma unroll
    for (int i = 0; i < 4; i++) {
        const int arr = i >> 1;                // 0 kh, 1 vh
        int rem = ((i & 1) << 8) + tid;        // 0..511
        int row = rem >> 3, q = rem & 7;
        const __half* g = (arr == 0 ? g_kh : g_vh) +
                          (krow0 + (size_t)kb * 64 + row) * HD + q * 8;
        CP_ASYNC(sbase + ABUF0 + buf * ABUF_B + arr * KTILE_B + row * ASTR_B + q * 16, g);
    }
}

__global__ __launch_bounds__(256, 2) void attn_mma(float* __restrict__ out)
{
    extern __shared__ char sma[];
    const uint32_t sbase = smem_to_u32(sma);
    const int tid = threadIdx.x, lane = tid & 31, wid = tid >> 5;
    const int qbi = gridDim.x - 1 - blockIdx.x;
    const int bh = blockIdx.y;
    const int kmax = 2 * qbi + 2;
    const size_t qrow0 = (size_t)bh * TSEQ + (size_t)qbi * 128;
    const size_t krow0 = (size_t)bh * TSEQ;

    // Q (fp16, pre-scaled) -> smem
#pragma unroll
    for (int i = 0; i < 4; i++) {
        int rem = (i << 8) + tid;               // 0..1023
        int row = rem >> 3, q = rem & 7;
        const __half* g = g_qh + (qrow0 + row) * HD + q * 8;
        CP_ASYNC(sbase + row * ASTR_B + q * 16, g);
    }
    CP_COMMIT();
    kv_load(sbase, tid, krow0, 0, 0);
    CP_COMMIT();
    CP_WAIT1();
    __syncthreads();

    uint32_t qfh[4][4];
#pragma unroll
    for (int ks = 0; ks < 4; ks++) {
        uint32_t a = sbase + (wid * 16 + (lane & 15)) * ASTR_B +
                     (ks * 16 + ((lane >> 4) << 3)) * 2;
        ldsm4(qfh[ks], a);
    }

    float o[8][4];
#pragma unroll
    for (int nj = 0; nj < 8; nj++)
#pragma unroll
        for (int c = 0; c < 4; c++) o[nj][c] = 0.f;
    float m1 = -1e30f, m2 = -1e30f, l1 = 0.f, l2 = 0.f;

    for (int kb = 0; kb < kmax; kb++) {
        const int buf = kb & 1;
        if (kb + 1 < kmax) {
            kv_load(sbase, tid, krow0, kb + 1, buf ^ 1);
            CP_COMMIT();
            CP_WAIT1();
        } else {
            CP_WAIT0();
        }
        __syncthreads();

        const bool active = (kb * 64 <= qbi * 128 + wid * 16 + 15);
        if (active) {
            // ---- S = qh * kh: 4-acc interleave ----
            float s[8][4];
#pragma unroll
            for (int nj = 0; nj < 8; nj++)
#pragma unroll
                for (int c = 0; c < 4; c++) s[nj][c] = 0.f;

            const uint32_t kbase = sbase + ABUF0 + buf * ABUF_B;
#pragma unroll
            for (int ks = 0; ks < 4; ks++) {
                const uint32_t coff = (ks * 16 + ((lane >> 4) << 3)) * 2;
#pragma unroll
                for (int gp = 0; gp < 2; gp++) {
                    uint32_t ka[4], kb4[4];
                    uint32_t ra = kbase + (gp * 32 + (lane & 15)) * ASTR_B + coff;
                    uint32_t rb = ra + 16 * ASTR_B;
                    ldsm4(ka,  ra);
                    ldsm4(kb4, rb);
                    mma_f16(s[4*gp+0], qfh[ks], ka[0],  ka[2]);
                    mma_f16(s[4*gp+1], qfh[ks], ka[1],  ka[3]);
                    mma_f16(s[4*gp+2], qfh[ks], kb4[0], kb4[2]);
                    mma_f16(s[4*gp+3], qfh[ks], kb4[1], kb4[3]);
                }
            }

            // ---- causal mask (diagonal band) ----
            if (kb >= 2 * qbi) {
                const int q1 = qbi * 128 + wid * 16 + (lane >> 2);
                const int tb = kb * 64 + 2 * (lane & 3);
#pragma unroll
                for (int nj = 0; nj < 8; nj++) {
                    const int t0 = tb + 8 * nj;
                    if (t0     > q1)     s[nj][0] = -1e30f;
                    if (t0 + 1 > q1)     s[nj][1] = -1e30f;
                    if (t0     > q1 + 8) s[nj][2] = -1e30f;
                    if (t0 + 1 > q1 + 8) s[nj][3] = -1e30f;
                }
            }

            // ---- online softmax, base-2 ----
            float mx1 = -1e30f, mx2 = -1e30f;
#pragma unroll
            for (int nj = 0; nj < 8; nj++) {
                mx1 = fmaxf(mx1, fmaxf(s[nj][0], s[nj][1]));
                mx2 = fmaxf(mx2, fmaxf(s[nj][2], s[nj][3]));
            }
            mx1 = fmaxf(mx1, __shfl_xor_sync(0xffffffffu, mx1, 1));
            mx1 = fmaxf(mx1, __shfl_xor_sync(0xffffffffu, mx1, 2));
            mx2 = fmaxf(mx2, __shfl_xor_sync(0xffffffffu, mx2, 1));
            mx2 = fmaxf(mx2, __shfl_xor_sync(0xffffffffu, mx2, 2));
            const float mn1 = fmaxf(m1, mx1), mn2 = fmaxf(m2, mx2);
            const float a1 = exp2f(m1 - mn1), a2 = exp2f(m2 - mn2);
            float rs1 = 0.f, rs2 = 0.f;
#pragma unroll
            for (int nj = 0; nj < 8; nj++) {
                s[nj][0] = exp2f(s[nj][0] - mn1);
                s[nj][1] = exp2f(s[nj][1] - mn1);
                s[nj][2] = exp2f(s[nj][2] - mn2);
                s[nj][3] = exp2f(s[nj][3] - mn2);
                rs1 += s[nj][0] + s[nj][1];
                rs2 += s[nj][2] + s[nj][3];
            }
            rs1 += __shfl_xor_sync(0xffffffffu, rs1, 1);
            rs1 += __shfl_xor_sync(0xffffffffu, rs1, 2);
            rs2 += __shfl_xor_sync(0xffffffffu, rs2, 1);
            rs2 += __shfl_xor_sync(0xffffffffu, rs2, 2);
            l1 = l1 * a1 + rs1;  l2 = l2 * a2 + rs2;
            m1 = mn1;            m2 = mn2;
#pragma unroll
            for (int nj = 0; nj < 8; nj++) {
                o[nj][0] *= a1; o[nj][1] *= a1;
                o[nj][2] *= a2; o[nj][3] *= a2;
            }

            // ---- O += P V (single fp16 MMA, 8-acc interleave) ----
            const uint32_t vbase = kbase + KTILE_B;
#pragma unroll
            for (int kt = 0; kt < 4; kt++) {
                uint32_t ph[4];
                {
                    const float* p0 = s[2 * kt];
                    const float* p1 = s[2 * kt + 1];
                    ph[0] = pack2h(__float2half(p0[0]), __float2half(p0[1]));
                    ph[1] = pack2h(__float2half(p0[2]), __float2half(p0[3]));
                    ph[2] = pack2h(__float2half(p1[0]), __float2half(p1[1]));
                    ph[3] = pack2h(__float2half(p1[2]), __float2half(p1[3]));
                }
#pragma unroll
                for (int g2 = 0; g2 < 4; g2++) {
                    uint32_t vh4[4];
                    uint32_t rb = vbase + (kt * 16 + (lane & 15)) * ASTR_B +
                                  (g2 * 16 + ((lane >> 4) << 3)) * 2;
                    ldsm4t(vh4, rb);
                    mma_f16(o[2*g2],   ph, vh4[0], vh4[1]);
                    mma_f16(o[2*g2+1], ph, vh4[2], vh4[3]);
                }
            }
        }
        __syncthreads();
    }

    // epilogue
    const float inv1 = 1.f / l1, inv2 = 1.f / l2;
    const int b = bh >> 4, h = bh & 15;
    const int t1 = qbi * 128 + wid * 16 + (lane >> 2);
    float* o1p = out + ((size_t)b * TSEQ + t1) * CDIM + h * 64 + 2 * (lane & 3);
    float* o2p = o1p + (size_t)8 * CDIM;
#pragma unroll
    for (int nj = 0; nj < 8; nj++) {
        *(float2*)(o1p + 8 * nj) = make_float2(o[nj][0] * inv1, o[nj][1] * inv1);
        *(float2*)(o2p + 8 * nj) = make_float2(o[nj][2] * inv2, o[nj][3] * inv2);
    }
}

// ---------------------------------------------------------------------------
extern "C" void kernel_launch(void* const* d_in, const int* in_sizes, int n_in,
                              void* d_out, int out_size)
{
    (void)in_sizes; (void)n_in; (void)out_size;
    const float* x  = (const float*)d_in[0];
    const float* w  = (const float*)d_in[1];
    const float* bb = (const float*)d_in[2];
    float* out = (float*)d_out;

    const int nx4 = BT * CDIM / 4;
    const int nw4 = NQKV * CDIM / 4;
    conv_all<<<(nx4 + nw4 + 255) / 256, 256>>>(x, w, nx4, nw4);

    const int gsmem = 2 * GSTAGE_B;                     // 40960
    cudaFuncSetAttribute((const void*)qkv_gemm_mma,
                         cudaFuncAttributeMaxDynamicSharedMemorySize, gsmem);
    dim3 gg(NQKV / 128, BT / 128);                      // (24, 64)
    qkv_gemm_mma<<<gg, 128, gsmem>>>(bb);

    const int asmem = ABUF0 + 2 * ABUF_B;               // 55296
    cudaFuncSetAttribute((const void*)attn_mma,
                         cudaFuncAttributeMaxDynamicSharedMemorySize, asmem);
    dim3 ga(TSEQ / 128, NB * HEADS);                    // (16, 64)
    attn_mma<<<ga, 256, asmem>>>(out);
}